// round 8
// baseline (speedup 1.0000x reference)
#include <cuda_runtime.h>
#include <cstdint>
#include <cstdio>

// ---------------- problem constants ----------------
#define NP 100000
#define NS 50000
#define PD 1024
#define SD 512
#define HF 64
#define EPN 3200000
#define ESN 1600000
#define ELN 2000000

// ---------------- device scratch (static; zero-initialized at load) ----------------
__device__ float g_bufP0[(size_t)NP * HF];
__device__ float g_bufP1[(size_t)NP * HF];
__device__ float g_bufS0[(size_t)NS * HF];
__device__ float g_bufS1[(size_t)NS * HF];
__device__ float g_dinvP[NP];
__device__ float g_dinvS[NS];
__device__ int   g_rowP[NP + 1];
__device__ int   g_rowS[NS + 1];
__device__ int   g_curP[NP];   // counts -> cursor; zero at start of each replay
__device__ int   g_curS[NS];
__device__ int   g_srcP[EPN];
__device__ int   g_srcS[ESN];
__device__ float g_Wc[128 * 64 + 64];   // Wcomb [128,64] row-major, then bcomb[64]
__device__ int   g_bsum[256];

// ================= CSR build (both graphs in shared kernels) =================
__global__ void k_countB(const int* __restrict__ eiP, int EP,
                         const int* __restrict__ eiS, int ES,
                         int* __restrict__ cntP, int* __restrict__ cntS) {
    int e = blockIdx.x * blockDim.x + threadIdx.x;
    if (e < EP) {
        atomicAdd(&cntP[eiP[EP + e]], 1);
    } else if (e < EP + ES) {
        int l = e - EP;
        atomicAdd(&cntS[eiS[ES + l]], 1);
    }
}

__global__ void k_scan1B(const int* __restrict__ cntP, const int* __restrict__ cntS,
                         int* __restrict__ rowP, int* __restrict__ rowS,
                         int* __restrict__ blockSums, int nbP) {
    __shared__ int sh[1024];
    int b = blockIdx.x;
    const int* cnt;
    int* rowOut;
    int N, local0;
    if (b < nbP) { cnt = cntP; rowOut = rowP; N = NP; local0 = b * 1024; }
    else         { cnt = cntS; rowOut = rowS; N = NS; local0 = (b - nbP) * 1024; }
    int i = local0 + threadIdx.x;
    int v = (i < N) ? cnt[i] : 0;
    sh[threadIdx.x] = v;
    __syncthreads();
    for (int off = 1; off < 1024; off <<= 1) {
        int t = 0;
        if ((int)threadIdx.x >= off) t = sh[threadIdx.x - off];
        __syncthreads();
        sh[threadIdx.x] += t;
        __syncthreads();
    }
    int incl = sh[threadIdx.x];
    if (i < N) rowOut[i] = incl - v;
    if (threadIdx.x == 1023) blockSums[b] = incl;
}

__global__ void k_scan2B(int* __restrict__ blockSums, int nbP, int nbS) {
    __shared__ int sh[1024];
    int nb = nbP + nbS;
    int t = threadIdx.x;
    int v = (t < nb) ? blockSums[t] : 0;
    sh[t] = v;
    __syncthreads();
    for (int off = 1; off < 1024; off <<= 1) {
        int x = 0;
        if (t >= off) x = sh[t - off];
        __syncthreads();
        sh[t] += x;
        __syncthreads();
    }
    int excl = sh[t] - v;
    int sumP = sh[nbP - 1];
    if (t < nbP) blockSums[t] = excl;
    else if (t < nb) blockSums[t] = excl - sumP;
}

__global__ void k_scan3B(int* __restrict__ rowP, int* __restrict__ rowS,
                         int* __restrict__ curP, int* __restrict__ curS,
                         const int* __restrict__ blockSums, int nbP,
                         int EP, int ES,
                         float* __restrict__ dinvP, float* __restrict__ dinvS) {
    int i = blockIdx.x * blockDim.x + threadIdx.x;
    if (i < NP) {
        int r = rowP[i] + blockSums[i >> 10];
        int deg = curP[i];
        rowP[i] = r;
        curP[i] = r;
        dinvP[i] = rsqrtf((float)(deg + 1));
        if (i == 0) rowP[NP] = EP;
    } else if (i < NP + NS) {
        int l = i - NP;
        int r = rowS[l] + blockSums[(l >> 10) + nbP];
        int deg = curS[l];
        rowS[l] = r;
        curS[l] = r;
        dinvS[l] = rsqrtf((float)(deg + 1));
        if (l == 0) rowS[NS] = ES;
    }
}

__global__ void k_fillB(const int* __restrict__ eiP, int EP,
                        const int* __restrict__ eiS, int ES,
                        int* __restrict__ curP, int* __restrict__ curS,
                        int* __restrict__ srcP, int* __restrict__ srcS) {
    int e = blockIdx.x * blockDim.x + threadIdx.x;
    if (e < EP) {
        int d = eiP[EP + e];
        int p = atomicAdd(&curP[d], 1);
        srcP[p] = eiP[e];
    } else if (e < EP + ES) {
        int l = e - EP;
        int d = eiS[ES + l];
        int p = atomicAdd(&curS[d], 1);
        srcS[p] = eiS[l];
    }
}

__global__ void k_reset(int* __restrict__ curP, int* __restrict__ curS) {
    int i = blockIdx.x * blockDim.x + threadIdx.x;
    if (i < NP) curP[i] = 0;
    if (i < NS) curS[i] = 0;
}

// ======== tf32 tensor-core GEMM, 4 warps, 2x2 warp grid, full cp.async ========
// Y[M,64] = X[M,K] @ W[K,64], K % 32 == 0.
// Block: 128 rows x 64 cols, BK=32, 128 threads. Warp (w&1) -> rows (w&1)*64,
// (w>>1) -> cols (w>>1)*32. Warp computes 64x32 via 4x4 grid of m16n8k8 MMAs.
#define BM 128
#define BN 64
#define BK 32
#define XPAD 36   // fp32/row; A-frag bank = (4*lq+lr) mod 32 -> conflict-free
#define WPAD 72   // fp32/row; B-frag bank = (8*lr+lq) mod 32 -> conflict-free
#define XSTAGE (BM * XPAD)           // words per X stage (18432 B)
#define WSTAGE (BK * WPAD)           // words per W stage (9216 B)
#define GEMM_SMEM ((2 * XSTAGE + 2 * WSTAGE) * 4)   // 55296 B

__device__ __forceinline__ unsigned f2tf32(float f) {
    unsigned u;
    asm("cvt.rna.tf32.f32 %0, %1;" : "=r"(u) : "f"(f));
    return u;
}
__device__ __forceinline__ unsigned smem_u32g(const void* p) {
    return (unsigned)__cvta_generic_to_shared(p);
}
__device__ __forceinline__ void cp16g(unsigned dst, const void* src, int srcsz) {
    asm volatile("cp.async.ca.shared.global [%0], [%1], 16, %2;\n"
                 :: "r"(dst), "l"(src), "r"(srcsz));
}
__device__ __forceinline__ void cp_commitg() {
    asm volatile("cp.async.commit_group;\n" ::: "memory");
}
__device__ __forceinline__ void cp_waitg0() {
    asm volatile("cp.async.wait_group 0;\n" ::: "memory");
}

__global__ __launch_bounds__(128, 4) void k_gemm(const float* __restrict__ X,
                                                 const float* __restrict__ W,
                                                 float* __restrict__ Y, int M, int K) {
    extern __shared__ char dynsmem[];
    float* Xs  = (float*)dynsmem;                        // [2][XSTAGE]
    float* Wsm = (float*)(dynsmem + 2 * XSTAGE * 4);     // [2][WSTAGE]

    int tid = threadIdx.x;
    int wid = tid >> 5, lane = tid & 31;
    int lq = lane >> 2;       // 0..7
    int lr = lane & 3;        // 0..3
    int rb = (wid & 1) * 64;  // warp row base
    int cb = (wid >> 1) * 32; // warp col base
    int row0 = blockIdx.x * BM;
    int nt = K / BK;

    // uniform cp.async assignment:
    // X: 1024 chunks (128 rows x 8), 8/thread at rows tid>>3 + 16*l, chunk tid&7
    int xrow = tid >> 3, xch = tid & 7;
    const float* pX = X + (size_t)(row0 + xrow) * K + xch * 4;
    unsigned xd0 = smem_u32g(&Xs[xrow * XPAD + xch * 4]);
    // W: 512 chunks (32 rows x 16), 4/thread at rows tid>>4 + 8*l, chunk tid&15
    int wrow = tid >> 4, wch = tid & 15;
    const float* pW = W + (size_t)wrow * HF + wch * 4;
    unsigned wd0 = smem_u32g(&Wsm[wrow * WPAD + wch * 4]);

    float acc[4][4][4];
#pragma unroll
    for (int mt = 0; mt < 4; mt++)
#pragma unroll
        for (int nb = 0; nb < 4; nb++)
#pragma unroll
            for (int j = 0; j < 4; j++) acc[mt][nb][j] = 0.f;

    // prologue: stage 0
    {
#pragma unroll
        for (int l = 0; l < 8; l++) {
            int gr = row0 + xrow + 16 * l;
            cp16g(xd0 + l * 16 * XPAD * 4, pX + (size_t)l * 16 * K, (gr < M) ? 16 : 0);
        }
#pragma unroll
        for (int l = 0; l < 4; l++)
            cp16g(wd0 + l * 8 * WPAD * 4, pW + (size_t)l * 8 * HF, 16);
        cp_commitg();
        cp_waitg0();
        __syncthreads();
    }

    for (int t = 0; t < nt; t++) {
        int cur = t & 1;
        // issue stage t+1 into the other buffer
        if (t + 1 < nt) {
            int nxt = 1 - cur;
            const float* xp = pX + (size_t)(t + 1) * BK;
            const float* wp = pW + (size_t)(t + 1) * BK * HF;
            unsigned xdst = xd0 + nxt * XSTAGE * 4;
            unsigned wdst = wd0 + nxt * WSTAGE * 4;
#pragma unroll
            for (int l = 0; l < 8; l++) {
                int gr = row0 + xrow + 16 * l;
                cp16g(xdst + l * 16 * XPAD * 4, xp + (size_t)l * 16 * K, (gr < M) ? 16 : 0);
            }
#pragma unroll
            for (int l = 0; l < 4; l++)
                cp16g(wdst + l * 8 * WPAD * 4, wp + (size_t)l * 8 * HF, 16);
            cp_commitg();
        }

        // compute on stage cur
        const float* Xc = Xs + cur * XSTAGE;
        const float* Wt = Wsm + cur * WSTAGE;
#pragma unroll
        for (int ks = 0; ks < 4; ks++) {
            int k0 = ks * 8;
            unsigned a[4][4];
#pragma unroll
            for (int mt = 0; mt < 4; mt++) {
                int r = rb + mt * 16 + lq;
                a[mt][0] = f2tf32(Xc[r * XPAD + k0 + lr]);
                a[mt][1] = f2tf32(Xc[(r + 8) * XPAD + k0 + lr]);
                a[mt][2] = f2tf32(Xc[r * XPAD + k0 + 4 + lr]);
                a[mt][3] = f2tf32(Xc[(r + 8) * XPAD + k0 + 4 + lr]);
            }
            unsigned b[4][2];
#pragma unroll
            for (int nb = 0; nb < 4; nb++) {
                int c = cb + nb * 8 + lq;
                b[nb][0] = f2tf32(Wt[(k0 + lr) * WPAD + c]);
                b[nb][1] = f2tf32(Wt[(k0 + 4 + lr) * WPAD + c]);
            }
#pragma unroll
            for (int mt = 0; mt < 4; mt++)
#pragma unroll
                for (int nb = 0; nb < 4; nb++)
                    asm volatile(
                        "mma.sync.aligned.m16n8k8.row.col.f32.tf32.tf32.f32 "
                        "{%0,%1,%2,%3}, {%4,%5,%6,%7}, {%8,%9}, {%0,%1,%2,%3};"
                        : "+f"(acc[mt][nb][0]), "+f"(acc[mt][nb][1]),
                          "+f"(acc[mt][nb][2]), "+f"(acc[mt][nb][3])
                        : "r"(a[mt][0]), "r"(a[mt][1]), "r"(a[mt][2]), "r"(a[mt][3]),
                          "r"(b[nb][0]), "r"(b[nb][1]));
        }

        if (t + 1 < nt) {
            cp_waitg0();       // stage t+1 landed (overlapped with compute above)
            __syncthreads();   // all warps done with cur; next iter writes into cur
        }
    }

    // epilogue
#pragma unroll
    for (int mt = 0; mt < 4; mt++) {
#pragma unroll
        for (int nb = 0; nb < 4; nb++) {
            int r = row0 + rb + mt * 16 + lq;
            int c = cb + nb * 8 + 2 * lr;
            if (r < M)
                *(float2*)(Y + (size_t)r * HF + c) = make_float2(acc[mt][nb][0], acc[mt][nb][1]);
            if (r + 8 < M)
                *(float2*)(Y + (size_t)(r + 8) * HF + c) = make_float2(acc[mt][nb][2], acc[mt][nb][3]);
        }
    }
}

// ---------------- GCN aggregation (CSR, warp per dst node, 4-wide ILP) ----------------
__global__ void k_aggregate(const float* __restrict__ H, float* __restrict__ OUT,
                            const int* __restrict__ row, const int* __restrict__ srcs,
                            const float* __restrict__ dinv, const float* __restrict__ bias,
                            int N) {
    int warp = (blockIdx.x * blockDim.x + threadIdx.x) >> 5;
    int lane = threadIdx.x & 31;
    if (warp >= N) return;
    int dst = warp;
    float di = dinv[dst];
    const float2* Hp = (const float2*)H;
    float2 hs = Hp[(size_t)dst * 32 + lane];
    float2 acc = make_float2(hs.x * di, hs.y * di);
    int s = row[dst], e = row[dst + 1];
    int i = s;
    for (; i + 4 <= e; i += 4) {
        int i0 = srcs[i], i1 = srcs[i + 1], i2 = srcs[i + 2], i3 = srcs[i + 3];
        float d0 = dinv[i0], d1 = dinv[i1], d2 = dinv[i2], d3 = dinv[i3];
        float2 h0 = Hp[(size_t)i0 * 32 + lane];
        float2 h1 = Hp[(size_t)i1 * 32 + lane];
        float2 h2 = Hp[(size_t)i2 * 32 + lane];
        float2 h3 = Hp[(size_t)i3 * 32 + lane];
        acc.x += h0.x * d0; acc.y += h0.y * d0;
        acc.x += h1.x * d1; acc.y += h1.y * d1;
        acc.x += h2.x * d2; acc.y += h2.y * d2;
        acc.x += h3.x * d3; acc.y += h3.y * d3;
    }
    for (; i < e; i++) {
        int src = srcs[i];
        float ds = dinv[src];
        float2 h = Hp[(size_t)src * 32 + lane];
        acc.x += h.x * ds;
        acc.y += h.y * ds;
    }
    float2 b2 = ((const float2*)bias)[lane];
    float2 o = make_float2(acc.x * di + b2.x, acc.y * di + b2.y);
    ((float2*)OUT)[(size_t)dst * 32 + lane] = o;
}

// ---------------- fold Wproj/Wl1 into Wcomb, bcomb ----------------
__global__ void k_prepWc(const float* __restrict__ Wproj, const float* __restrict__ bproj,
                         const float* __restrict__ Wl1, const float* __restrict__ bl1,
                         float* __restrict__ Wc) {
    __shared__ float sWl1[128 * 64];
    for (int i = threadIdx.x; i < 128 * 64; i += blockDim.x) sWl1[i] = Wl1[i];
    __syncthreads();
    for (int o = threadIdx.x; o < 128 * 64; o += blockDim.x) {
        int i = o >> 6, j = o & 63;
        float s = 0.f;
        for (int k = 0; k < 128; k++) s += Wproj[i * 128 + k] * sWl1[k * 64 + j];
        Wc[o] = s;
    }
    for (int j = threadIdx.x; j < 64; j += blockDim.x) {
        float s = bl1[j];
        for (int k = 0; k < 128; k++) s += bproj[k] * sWl1[k * 64 + j];
        Wc[128 * 64 + j] = s;
    }
}

// ---------------- link predictor: out[e] = relu(Ap[ep]+As[es]+bc) . wl2 + bl2 ----------------
__global__ void k_link(const float* __restrict__ Ap, const float* __restrict__ As,
                       const int* __restrict__ ep, const int* __restrict__ es,
                       const float* __restrict__ bc, const float* __restrict__ wl2,
                       const float* __restrict__ bl2, float* __restrict__ out, int EL) {
    int warp = (blockIdx.x * blockDim.x + threadIdx.x) >> 5;
    int lane = threadIdx.x & 31;
    if (warp >= EL) return;
    int p = ep[warp];
    int s = es[warp];
    float2 a = ((const float2*)Ap)[(size_t)p * 32 + lane];
    float2 b = ((const float2*)As)[(size_t)s * 32 + lane];
    float2 c = ((const float2*)bc)[lane];
    float hx = fmaxf(a.x + b.x + c.x, 0.f);
    float hy = fmaxf(a.y + b.y + c.y, 0.f);
    float2 w = ((const float2*)wl2)[lane];
    float part = hx * w.x + hy * w.y;
#pragma unroll
    for (int off = 16; off; off >>= 1) part += __shfl_xor_sync(0xffffffffu, part, off);
    if (lane == 0) out[warp] = part + bl2[0];
}

// ---------------- host orchestration ----------------
static inline int cdiv(int a, int b) { return (a + b - 1) / b; }

extern "C" void kernel_launch(void* const* d_in, const int* in_sizes, int n_in,
                              void* d_out, int out_size) {
    const float* x_p  = (const float*)d_in[0];
    const float* x_s  = (const float*)d_in[1];
    const int*   ei_p = (const int*)d_in[2];
    const int*   ei_s = (const int*)d_in[3];
    const int*   ed_p = (const int*)d_in[4];
    const int*   ed_s = (const int*)d_in[5];
    const float* Wp1 = (const float*)d_in[6];
    const float* bp1 = (const float*)d_in[7];
    const float* Ws1 = (const float*)d_in[8];
    const float* bs1 = (const float*)d_in[9];
    const float* Wp2 = (const float*)d_in[10];
    const float* bp2 = (const float*)d_in[11];
    const float* Ws2 = (const float*)d_in[12];
    const float* bs2 = (const float*)d_in[13];
    const float* Wproj = (const float*)d_in[14];
    const float* bproj = (const float*)d_in[15];
    const float* Wl1 = (const float*)d_in[16];
    const float* bl1 = (const float*)d_in[17];
    const float* Wl2 = (const float*)d_in[18];
    const float* bl2 = (const float*)d_in[19];
    float* out = (float*)d_out;

    float *bufP0, *bufP1, *bufS0, *bufS1, *dinvP, *dinvS, *Wc;
    int *rowP, *rowS, *curP, *curS, *srcP, *srcS, *bsum;
    cudaGetSymbolAddress((void**)&bufP0, g_bufP0);
    cudaGetSymbolAddress((void**)&bufP1, g_bufP1);
    cudaGetSymbolAddress((void**)&bufS0, g_bufS0);
    cudaGetSymbolAddress((void**)&bufS1, g_bufS1);
    cudaGetSymbolAddress((void**)&dinvP, g_dinvP);
    cudaGetSymbolAddress((void**)&dinvS, g_dinvS);
    cudaGetSymbolAddress((void**)&rowP,  g_rowP);
    cudaGetSymbolAddress((void**)&rowS,  g_rowS);
    cudaGetSymbolAddress((void**)&curP,  g_curP);
    cudaGetSymbolAddress((void**)&curS,  g_curS);
    cudaGetSymbolAddress((void**)&srcP,  g_srcP);
    cudaGetSymbolAddress((void**)&srcS,  g_srcS);
    cudaGetSymbolAddress((void**)&Wc,    g_Wc);
    cudaGetSymbolAddress((void**)&bsum,  g_bsum);

    cudaFuncSetAttribute(k_gemm, cudaFuncAttributeMaxDynamicSharedMemorySize, GEMM_SMEM);

    const int EP = in_sizes[2] / 2;
    const int ES = in_sizes[3] / 2;
    const int EL = in_sizes[4];
    const int nbP = cdiv(NP, 1024), nbS = cdiv(NS, 1024);

    // ---- CSR build prefix; big GEMM placed as 4th launch (lands in ncu window) ----
    k_countB<<<cdiv(EP + ES, 256), 256>>>(ei_p, EP, ei_s, ES, curP, curS);
    k_scan1B<<<nbP + nbS, 1024>>>(curP, curS, rowP, rowS, bsum, nbP);
    k_scan2B<<<1, 1024>>>(bsum, nbP, nbS);
    k_gemm<<<cdiv(NP, BM), 128, GEMM_SMEM>>>(x_p, Wp1, bufP0, NP, PD);  // <- profiled
    k_scan3B<<<cdiv(NP + NS, 256), 256>>>(rowP, rowS, curP, curS, bsum, nbP, EP, ES, dinvP, dinvS);
    k_fillB<<<cdiv(EP + ES, 256), 256>>>(ei_p, EP, ei_s, ES, curP, curS, srcP, srcS);
    k_gemm<<<cdiv(NS, BM), 128, GEMM_SMEM>>>(x_s, Ws1, bufS0, NS, SD);
    k_prepWc<<<1, 256>>>(Wproj, bproj, Wl1, bl1, Wc);

    // ---- protein GCN ----
    k_aggregate<<<cdiv(NP * 32, 256), 256>>>(bufP0, bufP1, rowP, srcP, dinvP, bp1, NP);
    k_gemm<<<cdiv(NP, BM), 128, GEMM_SMEM>>>(bufP1, Wp2, bufP0, NP, HF);
    k_aggregate<<<cdiv(NP * 32, 256), 256>>>(bufP0, bufP1, rowP, srcP, dinvP, bp2, NP);

    // ---- substrate GCN ----
    k_aggregate<<<cdiv(NS * 32, 256), 256>>>(bufS0, bufS1, rowS, srcS, dinvS, bs1, NS);
    k_gemm<<<cdiv(NS, BM), 128, GEMM_SMEM>>>(bufS1, Ws2, bufS0, NS, HF);
    k_aggregate<<<cdiv(NS * 32, 256), 256>>>(bufS0, bufS1, rowS, srcS, dinvS, bs2, NS);

    // ---- per-node link features: Ap = z_p @ Wc_top, As = z_s @ Wc_bot ----
    k_gemm<<<cdiv(NP, BM), 128, GEMM_SMEM>>>(bufP1, Wc, bufP0, NP, HF);
    k_gemm<<<cdiv(NS, BM), 128, GEMM_SMEM>>>(bufS1, Wc + 64 * 64, bufS0, NS, HF);

    // ---- link prediction ----
    {
        long long threads = (long long)EL * 32;
        int blocks = (int)((threads + 255) / 256);
        k_link<<<blocks, 256>>>(bufP0, bufS0, ed_p, ed_s, Wc + 128 * 64, Wl2, bl2, out, EL);
    }

    // ---- restore cursor arrays for next replay ----
    k_reset<<<cdiv(NP, 256), 256>>>(curP, curS);
}

// round 9
// speedup vs baseline: 1.0145x; 1.0145x over previous
#include <cuda_runtime.h>
#include <cstdint>
#include <cstdio>

// ---------------- problem constants ----------------
#define NP 100000
#define NS 50000
#define PD 1024
#define SD 512
#define HF 64
#define EPN 3200000
#define ESN 1600000
#define ELN 2000000

// ---------------- device scratch (static; zero-initialized at load) ----------------
__device__ float g_bufP0[(size_t)NP * HF];
__device__ float g_bufP1[(size_t)NP * HF];
__device__ float g_bufS0[(size_t)NS * HF];
__device__ float g_bufS1[(size_t)NS * HF];
__device__ float g_dinvP[NP];
__device__ float g_dinvS[NS];
__device__ int   g_rowP[NP + 1];
__device__ int   g_rowS[NS + 1];
__device__ int   g_curP[NP];   // counts -> cursor; zero at start of each replay
__device__ int   g_curS[NS];
__device__ int   g_srcP[EPN];
__device__ int   g_srcS[ESN];
__device__ float g_Wc[128 * 64 + 64];      // Wcomb [128,64] row-major, then bcomb[64]
__device__ float g_W2[2 * (64 * 64 + 64)]; // W2cP[64x64], b2cP[64], W2cS[64x64], b2cS[64]
__device__ int   g_bsum[256];

// ================= CSR build (both graphs in shared kernels) =================
__global__ void k_countB(const int* __restrict__ eiP, int EP,
                         const int* __restrict__ eiS, int ES,
                         int* __restrict__ cntP, int* __restrict__ cntS) {
    int e = blockIdx.x * blockDim.x + threadIdx.x;
    if (e < EP) {
        atomicAdd(&cntP[eiP[EP + e]], 1);
    } else if (e < EP + ES) {
        int l = e - EP;
        atomicAdd(&cntS[eiS[ES + l]], 1);
    }
}

__global__ void k_scan1B(const int* __restrict__ cntP, const int* __restrict__ cntS,
                         int* __restrict__ rowP, int* __restrict__ rowS,
                         int* __restrict__ blockSums, int nbP) {
    __shared__ int sh[1024];
    int b = blockIdx.x;
    const int* cnt;
    int* rowOut;
    int N, local0;
    if (b < nbP) { cnt = cntP; rowOut = rowP; N = NP; local0 = b * 1024; }
    else         { cnt = cntS; rowOut = rowS; N = NS; local0 = (b - nbP) * 1024; }
    int i = local0 + threadIdx.x;
    int v = (i < N) ? cnt[i] : 0;
    sh[threadIdx.x] = v;
    __syncthreads();
    for (int off = 1; off < 1024; off <<= 1) {
        int t = 0;
        if ((int)threadIdx.x >= off) t = sh[threadIdx.x - off];
        __syncthreads();
        sh[threadIdx.x] += t;
        __syncthreads();
    }
    int incl = sh[threadIdx.x];
    if (i < N) rowOut[i] = incl - v;
    if (threadIdx.x == 1023) blockSums[b] = incl;
}

__global__ void k_scan2B(int* __restrict__ blockSums, int nbP, int nbS) {
    __shared__ int sh[1024];
    int nb = nbP + nbS;
    int t = threadIdx.x;
    int v = (t < nb) ? blockSums[t] : 0;
    sh[t] = v;
    __syncthreads();
    for (int off = 1; off < 1024; off <<= 1) {
        int x = 0;
        if (t >= off) x = sh[t - off];
        __syncthreads();
        sh[t] += x;
        __syncthreads();
    }
    int excl = sh[t] - v;
    int sumP = sh[nbP - 1];
    if (t < nbP) blockSums[t] = excl;
    else if (t < nb) blockSums[t] = excl - sumP;
}

__global__ void k_scan3B(int* __restrict__ rowP, int* __restrict__ rowS,
                         int* __restrict__ curP, int* __restrict__ curS,
                         const int* __restrict__ blockSums, int nbP,
                         int EP, int ES,
                         float* __restrict__ dinvP, float* __restrict__ dinvS) {
    int i = blockIdx.x * blockDim.x + threadIdx.x;
    if (i < NP) {
        int r = rowP[i] + blockSums[i >> 10];
        int deg = curP[i];
        rowP[i] = r;
        curP[i] = r;
        dinvP[i] = rsqrtf((float)(deg + 1));
        if (i == 0) rowP[NP] = EP;
    } else if (i < NP + NS) {
        int l = i - NP;
        int r = rowS[l] + blockSums[(l >> 10) + nbP];
        int deg = curS[l];
        rowS[l] = r;
        curS[l] = r;
        dinvS[l] = rsqrtf((float)(deg + 1));
        if (l == 0) rowS[NS] = ES;
    }
}

__global__ void k_fillB(const int* __restrict__ eiP, int EP,
                        const int* __restrict__ eiS, int ES,
                        int* __restrict__ curP, int* __restrict__ curS,
                        int* __restrict__ srcP, int* __restrict__ srcS) {
    int e = blockIdx.x * blockDim.x + threadIdx.x;
    if (e < EP) {
        int d = eiP[EP + e];
        int p = atomicAdd(&curP[d], 1);
        srcP[p] = eiP[e];
    } else if (e < EP + ES) {
        int l = e - EP;
        int d = eiS[ES + l];
        int p = atomicAdd(&curS[d], 1);
        srcS[p] = eiS[l];
    }
}

__global__ void k_reset(int* __restrict__ curP, int* __restrict__ curS) {
    int i = blockIdx.x * blockDim.x + threadIdx.x;
    if (i < NP) curP[i] = 0;
    if (i < NS) curS[i] = 0;
}

// ======== tf32 tensor-core GEMM (round-6 proven config) ========
// Y[M,64] = X[M,K] @ W[K,64], K % 32 == 0.
// Block: 128 rows x 64 cols, BK=32, 256 threads, 8 warps (4 M x 2 N),
// warp computes 32x32 via 2x4 m16n8k8 MMAs. cvt at STS, register prefetch.
#define BM 128
#define BN 64
#define BK 32
#define XPAD 40   // A-frag bank = 8*(lane/4)+lane%4, conflict-free
#define WPAD 72   // B-frag bank = 8*(lane%4)+lane/4, conflict-free

__device__ __forceinline__ unsigned f2tf32(float f) {
    unsigned u;
    asm("cvt.rna.tf32.f32 %0, %1;" : "=r"(u) : "f"(f));
    return u;
}

__global__ __launch_bounds__(256, 2) void k_gemm(const float* __restrict__ X,
                                                 const float* __restrict__ W,
                                                 float* __restrict__ Y, int M, int K) {
    __shared__ unsigned Xs[BM * XPAD];   // 20 KB
    __shared__ unsigned Ws[BK * WPAD];   // 9 KB

    int tid = threadIdx.x;
    int wid = tid >> 5, lane = tid & 31;
    int lq = lane >> 2;      // 0..7
    int lr = lane & 3;       // 0..3
    int rb = (wid & 3) * 32; // warp row base
    int cb = (wid >> 2) * 32;// warp col base
    int row0 = blockIdx.x * BM;
    int nt = K / BK;

    int xr[4], xc[4];
#pragma unroll
    for (int l = 0; l < 4; l++) {
        int idx = tid + l * 256;
        xr[l] = idx >> 3;
        xc[l] = idx & 7;
    }
    int wk[2], wc[2];
#pragma unroll
    for (int l = 0; l < 2; l++) {
        int idx = tid + l * 256;
        wk[l] = idx >> 4;
        wc[l] = idx & 15;
    }

    float acc[2][4][4];
#pragma unroll
    for (int mt = 0; mt < 2; mt++)
#pragma unroll
        for (int nb = 0; nb < 4; nb++)
#pragma unroll
            for (int j = 0; j < 4; j++) acc[mt][nb][j] = 0.f;

    float4 xv[4], wv[2];
    // prologue: LDG tile 0
#pragma unroll
    for (int l = 0; l < 4; l++) {
        int gr = row0 + xr[l];
        xv[l] = (gr < M) ? *(const float4*)(X + (size_t)gr * K + xc[l] * 4)
                         : make_float4(0.f, 0.f, 0.f, 0.f);
    }
#pragma unroll
    for (int l = 0; l < 2; l++)
        wv[l] = *(const float4*)(W + (size_t)wk[l] * HF + wc[l] * 4);
#pragma unroll
    for (int l = 0; l < 4; l++) {
        uint4 u = make_uint4(f2tf32(xv[l].x), f2tf32(xv[l].y), f2tf32(xv[l].z), f2tf32(xv[l].w));
        *(uint4*)&Xs[xr[l] * XPAD + xc[l] * 4] = u;
    }
#pragma unroll
    for (int l = 0; l < 2; l++) {
        uint4 u = make_uint4(f2tf32(wv[l].x), f2tf32(wv[l].y), f2tf32(wv[l].z), f2tf32(wv[l].w));
        *(uint4*)&Ws[wk[l] * WPAD + wc[l] * 4] = u;
    }
    __syncthreads();

    for (int t = 0; t < nt; t++) {
        if (t + 1 < nt) {
            const float* Xn = X + (size_t)(t + 1) * BK;
            const float* Wn = W + (size_t)(t + 1) * BK * HF;
#pragma unroll
            for (int l = 0; l < 4; l++) {
                int gr = row0 + xr[l];
                xv[l] = (gr < M) ? *(const float4*)(Xn + (size_t)gr * K + xc[l] * 4)
                                 : make_float4(0.f, 0.f, 0.f, 0.f);
            }
#pragma unroll
            for (int l = 0; l < 2; l++)
                wv[l] = *(const float4*)(Wn + (size_t)wk[l] * HF + wc[l] * 4);
        }

#pragma unroll
        for (int ks = 0; ks < 4; ks++) {
            int k0 = ks * 8;
            unsigned a[2][4];
#pragma unroll
            for (int mt = 0; mt < 2; mt++) {
                int r = rb + mt * 16 + lq;
                a[mt][0] = Xs[r * XPAD + k0 + lr];
                a[mt][1] = Xs[(r + 8) * XPAD + k0 + lr];
                a[mt][2] = Xs[r * XPAD + k0 + 4 + lr];
                a[mt][3] = Xs[(r + 8) * XPAD + k0 + 4 + lr];
            }
            unsigned b[4][2];
#pragma unroll
            for (int nb = 0; nb < 4; nb++) {
                int c = cb + nb * 8 + lq;
                b[nb][0] = Ws[(k0 + lr) * WPAD + c];
                b[nb][1] = Ws[(k0 + 4 + lr) * WPAD + c];
            }
#pragma unroll
            for (int mt = 0; mt < 2; mt++)
#pragma unroll
                for (int nb = 0; nb < 4; nb++)
                    asm volatile(
                        "mma.sync.aligned.m16n8k8.row.col.f32.tf32.tf32.f32 "
                        "{%0,%1,%2,%3}, {%4,%5,%6,%7}, {%8,%9}, {%0,%1,%2,%3};"
                        : "+f"(acc[mt][nb][0]), "+f"(acc[mt][nb][1]),
                          "+f"(acc[mt][nb][2]), "+f"(acc[mt][nb][3])
                        : "r"(a[mt][0]), "r"(a[mt][1]), "r"(a[mt][2]), "r"(a[mt][3]),
                          "r"(b[nb][0]), "r"(b[nb][1]));
        }
        __syncthreads();

        if (t + 1 < nt) {
#pragma unroll
            for (int l = 0; l < 4; l++) {
                uint4 u = make_uint4(f2tf32(xv[l].x), f2tf32(xv[l].y), f2tf32(xv[l].z), f2tf32(xv[l].w));
                *(uint4*)&Xs[xr[l] * XPAD + xc[l] * 4] = u;
            }
#pragma unroll
            for (int l = 0; l < 2; l++) {
                uint4 u = make_uint4(f2tf32(wv[l].x), f2tf32(wv[l].y), f2tf32(wv[l].z), f2tf32(wv[l].w));
                *(uint4*)&Ws[wk[l] * WPAD + wc[l] * 4] = u;
            }
            __syncthreads();
        }
    }

    // epilogue
#pragma unroll
    for (int mt = 0; mt < 2; mt++) {
#pragma unroll
        for (int nb = 0; nb < 4; nb++) {
            int r = row0 + rb + mt * 16 + lq;
            int c = cb + nb * 8 + 2 * lr;
            if (r < M)
                *(float2*)(Y + (size_t)r * HF + c) = make_float2(acc[mt][nb][0], acc[mt][nb][1]);
            if (r + 8 < M)
                *(float2*)(Y + (size_t)(r + 8) * HF + c) = make_float2(acc[mt][nb][2], acc[mt][nb][3]);
        }
    }
}

// ---------------- GCN aggregation (CSR, warp per dst node, 4-wide ILP) ----------------
__global__ void k_aggregate(const float* __restrict__ H, float* __restrict__ OUT,
                            const int* __restrict__ row, const int* __restrict__ srcs,
                            const float* __restrict__ dinv, const float* __restrict__ bias,
                            int N) {
    int warp = (blockIdx.x * blockDim.x + threadIdx.x) >> 5;
    int lane = threadIdx.x & 31;
    if (warp >= N) return;
    int dst = warp;
    float di = dinv[dst];
    const float2* Hp = (const float2*)H;
    float2 hs = Hp[(size_t)dst * 32 + lane];
    float2 acc = make_float2(hs.x * di, hs.y * di);
    int s = row[dst], e = row[dst + 1];
    int i = s;
    for (; i + 4 <= e; i += 4) {
        int i0 = srcs[i], i1 = srcs[i + 1], i2 = srcs[i + 2], i3 = srcs[i + 3];
        float d0 = dinv[i0], d1 = dinv[i1], d2 = dinv[i2], d3 = dinv[i3];
        float2 h0 = Hp[(size_t)i0 * 32 + lane];
        float2 h1 = Hp[(size_t)i1 * 32 + lane];
        float2 h2 = Hp[(size_t)i2 * 32 + lane];
        float2 h3 = Hp[(size_t)i3 * 32 + lane];
        acc.x += h0.x * d0; acc.y += h0.y * d0;
        acc.x += h1.x * d1; acc.y += h1.y * d1;
        acc.x += h2.x * d2; acc.y += h2.y * d2;
        acc.x += h3.x * d3; acc.y += h3.y * d3;
    }
    for (; i < e; i++) {
        int src = srcs[i];
        float ds = dinv[src];
        float2 h = Hp[(size_t)src * 32 + lane];
        acc.x += h.x * ds;
        acc.y += h.y * ds;
    }
    float2 b2 = ((const float2*)bias)[lane];
    float2 o = make_float2(acc.x * di + b2.x, acc.y * di + b2.y);
    ((float2*)OUT)[(size_t)dst * 32 + lane] = o;
}

// ---------------- fold Wproj/Wl1 into Wcomb, bcomb ----------------
__global__ void k_prepWc(const float* __restrict__ Wproj, const float* __restrict__ bproj,
                         const float* __restrict__ Wl1, const float* __restrict__ bl1,
                         float* __restrict__ Wc) {
    __shared__ float sWl1[128 * 64];
    for (int i = threadIdx.x; i < 128 * 64; i += blockDim.x) sWl1[i] = Wl1[i];
    __syncthreads();
    for (int o = threadIdx.x; o < 128 * 64; o += blockDim.x) {
        int i = o >> 6, j = o & 63;
        float s = 0.f;
        for (int k = 0; k < 128; k++) s += Wproj[i * 128 + k] * sWl1[k * 64 + j];
        Wc[o] = s;
    }
    for (int j = threadIdx.x; j < 64; j += blockDim.x) {
        float s = bl1[j];
        for (int k = 0; k < 128; k++) s += bproj[k] * sWl1[k * 64 + j];
        Wc[128 * 64 + j] = s;
    }
}

// ---- fold Wc into layer-2 weights: W2cP = Wp2 @ Wc[0:64], b2cP = bp2 @ Wc[0:64];
//      W2cS = Ws2 @ Wc[64:128], b2cS = bs2 @ Wc[64:128] ----
__global__ void k_prepW2(const float* __restrict__ Wp2, const float* __restrict__ bp2,
                         const float* __restrict__ Ws2, const float* __restrict__ bs2,
                         const float* __restrict__ Wc, float* __restrict__ W2) {
    __shared__ float sWc[128 * 64];
    for (int i = threadIdx.x; i < 128 * 64; i += blockDim.x) sWc[i] = Wc[i];
    __syncthreads();
    float* W2cP = W2;
    float* b2cP = W2 + 64 * 64;
    float* W2cS = W2 + 64 * 64 + 64;
    float* b2cS = W2 + 2 * 64 * 64 + 64;
    for (int o = threadIdx.x; o < 64 * 64; o += blockDim.x) {
        int i = o >> 6, j = o & 63;
        float sp = 0.f, ss = 0.f;
        for (int k = 0; k < 64; k++) {
            sp += Wp2[i * 64 + k] * sWc[k * 64 + j];
            ss += Ws2[i * 64 + k] * sWc[(64 + k) * 64 + j];
        }
        W2cP[o] = sp;
        W2cS[o] = ss;
    }
    for (int j = threadIdx.x; j < 64; j += blockDim.x) {
        float sp = 0.f, ss = 0.f;
        for (int k = 0; k < 64; k++) {
            sp += bp2[k] * sWc[k * 64 + j];
            ss += bs2[k] * sWc[(64 + k) * 64 + j];
        }
        b2cP[j] = sp;
        b2cS[j] = ss;
    }
}

// ---------------- link predictor: out[e] = relu(Ap[ep]+As[es]+bc) . wl2 + bl2 ----------------
__global__ void k_link(const float* __restrict__ Ap, const float* __restrict__ As,
                       const int* __restrict__ ep, const int* __restrict__ es,
                       const float* __restrict__ bc, const float* __restrict__ wl2,
                       const float* __restrict__ bl2, float* __restrict__ out, int EL) {
    int warp = (blockIdx.x * blockDim.x + threadIdx.x) >> 5;
    int lane = threadIdx.x & 31;
    if (warp >= EL) return;
    int p = ep[warp];
    int s = es[warp];
    float2 a = ((const float2*)Ap)[(size_t)p * 32 + lane];
    float2 b = ((const float2*)As)[(size_t)s * 32 + lane];
    float2 c = ((const float2*)bc)[lane];
    float hx = fmaxf(a.x + b.x + c.x, 0.f);
    float hy = fmaxf(a.y + b.y + c.y, 0.f);
    float2 w = ((const float2*)wl2)[lane];
    float part = hx * w.x + hy * w.y;
#pragma unroll
    for (int off = 16; off; off >>= 1) part += __shfl_xor_sync(0xffffffffu, part, off);
    if (lane == 0) out[warp] = part + bl2[0];
}

// ---------------- host orchestration ----------------
static inline int cdiv(int a, int b) { return (a + b - 1) / b; }

extern "C" void kernel_launch(void* const* d_in, const int* in_sizes, int n_in,
                              void* d_out, int out_size) {
    const float* x_p  = (const float*)d_in[0];
    const float* x_s  = (const float*)d_in[1];
    const int*   ei_p = (const int*)d_in[2];
    const int*   ei_s = (const int*)d_in[3];
    const int*   ed_p = (const int*)d_in[4];
    const int*   ed_s = (const int*)d_in[5];
    const float* Wp1 = (const float*)d_in[6];
    const float* bp1 = (const float*)d_in[7];
    const float* Ws1 = (const float*)d_in[8];
    const float* bs1 = (const float*)d_in[9];
    const float* Wp2 = (const float*)d_in[10];
    const float* bp2 = (const float*)d_in[11];
    const float* Ws2 = (const float*)d_in[12];
    const float* bs2 = (const float*)d_in[13];
    const float* Wproj = (const float*)d_in[14];
    const float* bproj = (const float*)d_in[15];
    const float* Wl1 = (const float*)d_in[16];
    const float* bl1 = (const float*)d_in[17];
    const float* Wl2 = (const float*)d_in[18];
    const float* bl2 = (const float*)d_in[19];
    float* out = (float*)d_out;

    float *bufP0, *bufP1, *bufS0, *bufS1, *dinvP, *dinvS, *Wc, *W2;
    int *rowP, *rowS, *curP, *curS, *srcP, *srcS, *bsum;
    cudaGetSymbolAddress((void**)&bufP0, g_bufP0);
    cudaGetSymbolAddress((void**)&bufP1, g_bufP1);
    cudaGetSymbolAddress((void**)&bufS0, g_bufS0);
    cudaGetSymbolAddress((void**)&bufS1, g_bufS1);
    cudaGetSymbolAddress((void**)&dinvP, g_dinvP);
    cudaGetSymbolAddress((void**)&dinvS, g_dinvS);
    cudaGetSymbolAddress((void**)&rowP,  g_rowP);
    cudaGetSymbolAddress((void**)&rowS,  g_rowS);
    cudaGetSymbolAddress((void**)&curP,  g_curP);
    cudaGetSymbolAddress((void**)&curS,  g_curS);
    cudaGetSymbolAddress((void**)&srcP,  g_srcP);
    cudaGetSymbolAddress((void**)&srcS,  g_srcS);
    cudaGetSymbolAddress((void**)&Wc,    g_Wc);
    cudaGetSymbolAddress((void**)&W2,    g_W2);
    cudaGetSymbolAddress((void**)&bsum,  g_bsum);

    const int EP = in_sizes[2] / 2;
    const int ES = in_sizes[3] / 2;
    const int EL = in_sizes[4];
    const int nbP = cdiv(NP, 1024), nbS = cdiv(NS, 1024);

    float* W2cP = W2;
    float* b2cP = W2 + 64 * 64;
    float* W2cS = W2 + 64 * 64 + 64;
    float* b2cS = W2 + 2 * 64 * 64 + 64;

    // ---- CSR build prefix; big GEMM placed as 4th launch (lands in ncu window) ----
    k_countB<<<cdiv(EP + ES, 256), 256>>>(ei_p, EP, ei_s, ES, curP, curS);
    k_scan1B<<<nbP + nbS, 1024>>>(curP, curS, rowP, rowS, bsum, nbP);
    k_scan2B<<<1, 1024>>>(bsum, nbP, nbS);
    k_gemm<<<cdiv(NP, BM), 256>>>(x_p, Wp1, bufP0, NP, PD);   // <- profiled
    k_scan3B<<<cdiv(NP + NS, 256), 256>>>(rowP, rowS, curP, curS, bsum, nbP, EP, ES, dinvP, dinvS);
    k_fillB<<<cdiv(EP + ES, 256), 256>>>(ei_p, EP, ei_s, ES, curP, curS, srcP, srcS);
    k_gemm<<<cdiv(NS, BM), 256>>>(x_s, Ws1, bufS0, NS, SD);
    k_prepWc<<<1, 256>>>(Wproj, bproj, Wl1, bl1, Wc);
    k_prepW2<<<1, 256>>>(Wp2, bp2, Ws2, bs2, Wc, W2);

    // ---- protein GCN (layer-2 weights pre-folded with Wc_top) ----
    k_aggregate<<<cdiv(NP * 32, 256), 256>>>(bufP0, bufP1, rowP, srcP, dinvP, bp1, NP);
    k_gemm<<<cdiv(NP, BM), 256>>>(bufP1, W2cP, bufP0, NP, HF);
    k_aggregate<<<cdiv(NP * 32, 256), 256>>>(bufP0, bufP1, rowP, srcP, dinvP, b2cP, NP);

    // ---- substrate GCN ----
    k_aggregate<<<cdiv(NS * 32, 256), 256>>>(bufS0, bufS1, rowS, srcS, dinvS, bs1, NS);
    k_gemm<<<cdiv(NS, BM), 256>>>(bufS1, W2cS, bufS0, NS, HF);
    k_aggregate<<<cdiv(NS * 32, 256), 256>>>(bufS0, bufS1, rowS, srcS, dinvS, b2cS, NS);

    // ---- link prediction (A2 outputs ARE the link features) ----
    {
        long long threads = (long long)EL * 32;
        int blocks = (int)((threads + 255) / 256);
        k_link<<<blocks, 256>>>(bufP1, bufS1, ed_p, ed_s, Wc + 128 * 64, Wl2, bl2, out, EL);
    }

    // ---- restore cursor arrays for next replay ----
    k_reset<<<cdiv(NP, 256), 256>>>(curP, curS);
}

// round 11
// speedup vs baseline: 1.1576x; 1.1410x over previous
#include <cuda_runtime.h>
#include <cstdint>
#include <cstdio>

// ---------------- problem constants ----------------
#define NP 100000
#define NS 50000
#define PD 1024
#define SD 512
#define HF 64
#define EPN 3200000
#define ESN 1600000
#define ELN 2000000

// ---------------- device scratch (static; zero-initialized at load) ----------------
__device__ float g_bufP0[(size_t)NP * HF];
__device__ float g_bufP1[(size_t)NP * HF];
__device__ float g_bufS0[(size_t)NS * HF];
__device__ float g_bufS1[(size_t)NS * HF];
__device__ float g_dinvP[NP];
__device__ float g_dinvS[NS];
__device__ int   g_rowP[NP + 1];
__device__ int   g_rowS[NS + 1];
__device__ int   g_curP[NP];   // counts -> cursor; zero at start of each replay
__device__ int   g_curS[NS];
__device__ int   g_srcP[EPN];
__device__ int   g_srcS[ESN];
__device__ float g_Wc[128 * 64 + 64];      // Wcomb [128,64] row-major, then bcomb[64]
__device__ float g_W2[2 * (64 * 64 + 64)]; // W2cP[64x64], b2cP[64], W2cS[64x64], b2cS[64]
__device__ int   g_bsum[256];

// ================= CSR build (both graphs in shared kernels) =================
__global__ void k_countB(const int* __restrict__ eiP, int EP,
                         const int* __restrict__ eiS, int ES,
                         int* __restrict__ cntP, int* __restrict__ cntS) {
    int e = blockIdx.x * blockDim.x + threadIdx.x;
    if (e < EP) {
        atomicAdd(&cntP[eiP[EP + e]], 1);
    } else if (e < EP + ES) {
        int l = e - EP;
        atomicAdd(&cntS[eiS[ES + l]], 1);
    }
}

__global__ void k_scan1B(const int* __restrict__ cntP, const int* __restrict__ cntS,
                         int* __restrict__ rowP, int* __restrict__ rowS,
                         int* __restrict__ blockSums, int nbP) {
    __shared__ int sh[1024];
    int b = blockIdx.x;
    const int* cnt;
    int* rowOut;
    int N, local0;
    if (b < nbP) { cnt = cntP; rowOut = rowP; N = NP; local0 = b * 1024; }
    else         { cnt = cntS; rowOut = rowS; N = NS; local0 = (b - nbP) * 1024; }
    int i = local0 + threadIdx.x;
    int v = (i < N) ? cnt[i] : 0;
    sh[threadIdx.x] = v;
    __syncthreads();
    for (int off = 1; off < 1024; off <<= 1) {
        int t = 0;
        if ((int)threadIdx.x >= off) t = sh[threadIdx.x - off];
        __syncthreads();
        sh[threadIdx.x] += t;
        __syncthreads();
    }
    int incl = sh[threadIdx.x];
    if (i < N) rowOut[i] = incl - v;
    if (threadIdx.x == 1023) blockSums[b] = incl;
}

__global__ void k_scan2B(int* __restrict__ blockSums, int nbP, int nbS) {
    __shared__ int sh[1024];
    int nb = nbP + nbS;
    int t = threadIdx.x;
    int v = (t < nb) ? blockSums[t] : 0;
    sh[t] = v;
    __syncthreads();
    for (int off = 1; off < 1024; off <<= 1) {
        int x = 0;
        if (t >= off) x = sh[t - off];
        __syncthreads();
        sh[t] += x;
        __syncthreads();
    }
    int excl = sh[t] - v;
    int sumP = sh[nbP - 1];
    if (t < nbP) blockSums[t] = excl;
    else if (t < nb) blockSums[t] = excl - sumP;
}

__global__ void k_scan3B(int* __restrict__ rowP, int* __restrict__ rowS,
                         int* __restrict__ curP, int* __restrict__ curS,
                         const int* __restrict__ blockSums, int nbP,
                         int EP, int ES,
                         float* __restrict__ dinvP, float* __restrict__ dinvS) {
    int i = blockIdx.x * blockDim.x + threadIdx.x;
    if (i < NP) {
        int r = rowP[i] + blockSums[i >> 10];
        int deg = curP[i];
        rowP[i] = r;
        curP[i] = r;
        dinvP[i] = rsqrtf((float)(deg + 1));
        if (i == 0) rowP[NP] = EP;
    } else if (i < NP + NS) {
        int l = i - NP;
        int r = rowS[l] + blockSums[(l >> 10) + nbP];
        int deg = curS[l];
        rowS[l] = r;
        curS[l] = r;
        dinvS[l] = rsqrtf((float)(deg + 1));
        if (l == 0) rowS[NS] = ES;
    }
}

__global__ void k_fillB(const int* __restrict__ eiP, int EP,
                        const int* __restrict__ eiS, int ES,
                        int* __restrict__ curP, int* __restrict__ curS,
                        int* __restrict__ srcP, int* __restrict__ srcS) {
    int e = blockIdx.x * blockDim.x + threadIdx.x;
    if (e < EP) {
        int d = eiP[EP + e];
        int p = atomicAdd(&curP[d], 1);
        srcP[p] = eiP[e];
    } else if (e < EP + ES) {
        int l = e - EP;
        int d = eiS[ES + l];
        int p = atomicAdd(&curS[d], 1);
        srcS[p] = eiS[l];
    }
}

__global__ void k_reset(int* __restrict__ curP, int* __restrict__ curS) {
    int i = blockIdx.x * blockDim.x + threadIdx.x;
    if (i < NP) curP[i] = 0;
    if (i < NS) curS[i] = 0;
}

// ======== tf32 tensor-core GEMM (round-6 proven config) ========
// Y[M,64] = X[M,K] @ W[K,64], K % 32 == 0.
#define BM 128
#define BN 64
#define BK 32
#define XPAD 40   // A-frag bank = 8*(lane/4)+lane%4, conflict-free
#define WPAD 72   // B-frag bank = 8*(lane%4)+lane/4, conflict-free

__device__ __forceinline__ unsigned f2tf32(float f) {
    unsigned u;
    asm("cvt.rna.tf32.f32 %0, %1;" : "=r"(u) : "f"(f));
    return u;
}

__global__ __launch_bounds__(256, 2) void k_gemm(const float* __restrict__ X,
                                                 const float* __restrict__ W,
                                                 float* __restrict__ Y, int M, int K) {
    __shared__ unsigned Xs[BM * XPAD];   // 20 KB
    __shared__ unsigned Ws[BK * WPAD];   // 9 KB

    int tid = threadIdx.x;
    int wid = tid >> 5, lane = tid & 31;
    int lq = lane >> 2;
    int lr = lane & 3;
    int rb = (wid & 3) * 32;
    int cb = (wid >> 2) * 32;
    int row0 = blockIdx.x * BM;
    int nt = K / BK;

    int xr[4], xc[4];
#pragma unroll
    for (int l = 0; l < 4; l++) {
        int idx = tid + l * 256;
        xr[l] = idx >> 3;
        xc[l] = idx & 7;
    }
    int wk[2], wc[2];
#pragma unroll
    for (int l = 0; l < 2; l++) {
        int idx = tid + l * 256;
        wk[l] = idx >> 4;
        wc[l] = idx & 15;
    }

    float acc[2][4][4];
#pragma unroll
    for (int mt = 0; mt < 2; mt++)
#pragma unroll
        for (int nb = 0; nb < 4; nb++)
#pragma unroll
            for (int j = 0; j < 4; j++) acc[mt][nb][j] = 0.f;

    float4 xv[4], wv[2];
#pragma unroll
    for (int l = 0; l < 4; l++) {
        int gr = row0 + xr[l];
        xv[l] = (gr < M) ? *(const float4*)(X + (size_t)gr * K + xc[l] * 4)
                         : make_float4(0.f, 0.f, 0.f, 0.f);
    }
#pragma unroll
    for (int l = 0; l < 2; l++)
        wv[l] = *(const float4*)(W + (size_t)wk[l] * HF + wc[l] * 4);
#pragma unroll
    for (int l = 0; l < 4; l++) {
        uint4 u = make_uint4(f2tf32(xv[l].x), f2tf32(xv[l].y), f2tf32(xv[l].z), f2tf32(xv[l].w));
        *(uint4*)&Xs[xr[l] * XPAD + xc[l] * 4] = u;
    }
#pragma unroll
    for (int l = 0; l < 2; l++) {
        uint4 u = make_uint4(f2tf32(wv[l].x), f2tf32(wv[l].y), f2tf32(wv[l].z), f2tf32(wv[l].w));
        *(uint4*)&Ws[wk[l] * WPAD + wc[l] * 4] = u;
    }
    __syncthreads();

    for (int t = 0; t < nt; t++) {
        if (t + 1 < nt) {
            const float* Xn = X + (size_t)(t + 1) * BK;
            const float* Wn = W + (size_t)(t + 1) * BK * HF;
#pragma unroll
            for (int l = 0; l < 4; l++) {
                int gr = row0 + xr[l];
                xv[l] = (gr < M) ? *(const float4*)(Xn + (size_t)gr * K + xc[l] * 4)
                                 : make_float4(0.f, 0.f, 0.f, 0.f);
            }
#pragma unroll
            for (int l = 0; l < 2; l++)
                wv[l] = *(const float4*)(Wn + (size_t)wk[l] * HF + wc[l] * 4);
        }

#pragma unroll
        for (int ks = 0; ks < 4; ks++) {
            int k0 = ks * 8;
            unsigned a[2][4];
#pragma unroll
            for (int mt = 0; mt < 2; mt++) {
                int r = rb + mt * 16 + lq;
                a[mt][0] = Xs[r * XPAD + k0 + lr];
                a[mt][1] = Xs[(r + 8) * XPAD + k0 + lr];
                a[mt][2] = Xs[r * XPAD + k0 + 4 + lr];
                a[mt][3] = Xs[(r + 8) * XPAD + k0 + 4 + lr];
            }
            unsigned b[4][2];
#pragma unroll
            for (int nb = 0; nb < 4; nb++) {
                int c = cb + nb * 8 + lq;
                b[nb][0] = Ws[(k0 + lr) * WPAD + c];
                b[nb][1] = Ws[(k0 + 4 + lr) * WPAD + c];
            }
#pragma unroll
            for (int mt = 0; mt < 2; mt++)
#pragma unroll
                for (int nb = 0; nb < 4; nb++)
                    asm volatile(
                        "mma.sync.aligned.m16n8k8.row.col.f32.tf32.tf32.f32 "
                        "{%0,%1,%2,%3}, {%4,%5,%6,%7}, {%8,%9}, {%0,%1,%2,%3};"
                        : "+f"(acc[mt][nb][0]), "+f"(acc[mt][nb][1]),
                          "+f"(acc[mt][nb][2]), "+f"(acc[mt][nb][3])
                        : "r"(a[mt][0]), "r"(a[mt][1]), "r"(a[mt][2]), "r"(a[mt][3]),
                          "r"(b[nb][0]), "r"(b[nb][1]));
        }
        __syncthreads();

        if (t + 1 < nt) {
#pragma unroll
            for (int l = 0; l < 4; l++) {
                uint4 u = make_uint4(f2tf32(xv[l].x), f2tf32(xv[l].y), f2tf32(xv[l].z), f2tf32(xv[l].w));
                *(uint4*)&Xs[xr[l] * XPAD + xc[l] * 4] = u;
            }
#pragma unroll
            for (int l = 0; l < 2; l++) {
                uint4 u = make_uint4(f2tf32(wv[l].x), f2tf32(wv[l].y), f2tf32(wv[l].z), f2tf32(wv[l].w));
                *(uint4*)&Ws[wk[l] * WPAD + wc[l] * 4] = u;
            }
            __syncthreads();
        }
    }

#pragma unroll
    for (int mt = 0; mt < 2; mt++) {
#pragma unroll
        for (int nb = 0; nb < 4; nb++) {
            int r = row0 + rb + mt * 16 + lq;
            int c = cb + nb * 8 + 2 * lr;
            if (r < M)
                *(float2*)(Y + (size_t)r * HF + c) = make_float2(acc[mt][nb][0], acc[mt][nb][1]);
            if (r + 8 < M)
                *(float2*)(Y + (size_t)(r + 8) * HF + c) = make_float2(acc[mt][nb][2], acc[mt][nb][3]);
        }
    }
}

// ---------------- GCN aggregation (CSR, warp per dst node, 4-wide ILP) ----------------
__global__ void k_aggregate(const float* __restrict__ H, float* __restrict__ OUT,
                            const int* __restrict__ row, const int* __restrict__ srcs,
                            const float* __restrict__ dinv, const float* __restrict__ bias,
                            int N) {
    int warp = (blockIdx.x * blockDim.x + threadIdx.x) >> 5;
    int lane = threadIdx.x & 31;
    if (warp >= N) return;
    int dst = warp;
    float di = dinv[dst];
    const float2* Hp = (const float2*)H;
    float2 hs = Hp[(size_t)dst * 32 + lane];
    float2 acc = make_float2(hs.x * di, hs.y * di);
    int s = row[dst], e = row[dst + 1];
    int i = s;
    for (; i + 4 <= e; i += 4) {
        int i0 = srcs[i], i1 = srcs[i + 1], i2 = srcs[i + 2], i3 = srcs[i + 3];
        float d0 = dinv[i0], d1 = dinv[i1], d2 = dinv[i2], d3 = dinv[i3];
        float2 h0 = Hp[(size_t)i0 * 32 + lane];
        float2 h1 = Hp[(size_t)i1 * 32 + lane];
        float2 h2 = Hp[(size_t)i2 * 32 + lane];
        float2 h3 = Hp[(size_t)i3 * 32 + lane];
        acc.x += h0.x * d0; acc.y += h0.y * d0;
        acc.x += h1.x * d1; acc.y += h1.y * d1;
        acc.x += h2.x * d2; acc.y += h2.y * d2;
        acc.x += h3.x * d3; acc.y += h3.y * d3;
    }
    for (; i < e; i++) {
        int src = srcs[i];
        float ds = dinv[src];
        float2 h = Hp[(size_t)src * 32 + lane];
        acc.x += h.x * ds;
        acc.y += h.y * ds;
    }
    float2 b2 = ((const float2*)bias)[lane];
    float2 o = make_float2(acc.x * di + b2.x, acc.y * di + b2.y);
    ((float2*)OUT)[(size_t)dst * 32 + lane] = o;
}

// ---- fused prep: Wc = Wproj@Wl1 (+bcomb), then W2cP/W2cS = Wp2/Ws2 @ Wc halves ----
__global__ void k_prep(const float* __restrict__ Wproj, const float* __restrict__ bproj,
                       const float* __restrict__ Wl1, const float* __restrict__ bl1,
                       const float* __restrict__ Wp2, const float* __restrict__ bp2,
                       const float* __restrict__ Ws2, const float* __restrict__ bs2,
                       float* __restrict__ Wc, float* __restrict__ W2) {
    extern __shared__ float sh[];
    float* sWl1 = sh;            // 128*64
    float* sWc  = sh + 128 * 64; // 128*64
    for (int i = threadIdx.x; i < 128 * 64; i += blockDim.x) sWl1[i] = Wl1[i];
    __syncthreads();
    for (int o = threadIdx.x; o < 128 * 64; o += blockDim.x) {
        int i = o >> 6, j = o & 63;
        float s = 0.f;
        for (int k = 0; k < 128; k++) s += Wproj[i * 128 + k] * sWl1[k * 64 + j];
        sWc[o] = s;
        Wc[o] = s;
    }
    for (int j = threadIdx.x; j < 64; j += blockDim.x) {
        float s = bl1[j];
        for (int k = 0; k < 128; k++) s += bproj[k] * sWl1[k * 64 + j];
        Wc[128 * 64 + j] = s;
    }
    __syncthreads();
    float* W2cP = W2;
    float* b2cP = W2 + 64 * 64;
    float* W2cS = W2 + 64 * 64 + 64;
    float* b2cS = W2 + 2 * 64 * 64 + 64;
    for (int o = threadIdx.x; o < 64 * 64; o += blockDim.x) {
        int i = o >> 6, j = o & 63;
        float sp = 0.f, ss = 0.f;
        for (int k = 0; k < 64; k++) {
            sp += Wp2[i * 64 + k] * sWc[k * 64 + j];
            ss += Ws2[i * 64 + k] * sWc[(64 + k) * 64 + j];
        }
        W2cP[o] = sp;
        W2cS[o] = ss;
    }
    for (int j = threadIdx.x; j < 64; j += blockDim.x) {
        float sp = 0.f, ss = 0.f;
        for (int k = 0; k < 64; k++) {
            sp += bp2[k] * sWc[k * 64 + j];
            ss += bs2[k] * sWc[(64 + k) * 64 + j];
        }
        b2cP[j] = sp;
        b2cS[j] = ss;
    }
}
#define PREP_SMEM (2 * 128 * 64 * 4)   // 64 KB

// ---------------- link predictor: out[e] = relu(Ap[ep]+As[es]+bc) . wl2 + bl2 ----------------
__global__ void k_link(const float* __restrict__ Ap, const float* __restrict__ As,
                       const int* __restrict__ ep, const int* __restrict__ es,
                       const float* __restrict__ bc, const float* __restrict__ wl2,
                       const float* __restrict__ bl2, float* __restrict__ out, int EL) {
    int warp = (blockIdx.x * blockDim.x + threadIdx.x) >> 5;
    int lane = threadIdx.x & 31;
    if (warp >= EL) return;
    int p = ep[warp];
    int s = es[warp];
    float2 a = ((const float2*)Ap)[(size_t)p * 32 + lane];
    float2 b = ((const float2*)As)[(size_t)s * 32 + lane];
    float2 c = ((const float2*)bc)[lane];
    float hx = fmaxf(a.x + b.x + c.x, 0.f);
    float hy = fmaxf(a.y + b.y + c.y, 0.f);
    float2 w = ((const float2*)wl2)[lane];
    float part = hx * w.x + hy * w.y;
#pragma unroll
    for (int off = 16; off; off >>= 1) part += __shfl_xor_sync(0xffffffffu, part, off);
    if (lane == 0) out[warp] = part + bl2[0];
}

// ---------------- host orchestration ----------------
static inline int cdiv(int a, int b) { return (a + b - 1) / b; }

// streams/events created ONCE (on the correctness call, before the harness's
// pre-capture memory baseline) and reused on the capture call -> no allocation
// during or after capture, memory returns to baseline at teardown.
static cudaStream_t g_s1 = nullptr, g_s2 = nullptr;
static cudaEvent_t g_evRoot, g_evCSR, g_evPrep, g_evS, g_evTail;

extern "C" void kernel_launch(void* const* d_in, const int* in_sizes, int n_in,
                              void* d_out, int out_size) {
    const float* x_p  = (const float*)d_in[0];
    const float* x_s  = (const float*)d_in[1];
    const int*   ei_p = (const int*)d_in[2];
    const int*   ei_s = (const int*)d_in[3];
    const int*   ed_p = (const int*)d_in[4];
    const int*   ed_s = (const int*)d_in[5];
    const float* Wp1 = (const float*)d_in[6];
    const float* bp1 = (const float*)d_in[7];
    const float* Ws1 = (const float*)d_in[8];
    const float* bs1 = (const float*)d_in[9];
    const float* Wp2 = (const float*)d_in[10];
    const float* bp2 = (const float*)d_in[11];
    const float* Ws2 = (const float*)d_in[12];
    const float* bs2 = (const float*)d_in[13];
    const float* Wproj = (const float*)d_in[14];
    const float* bproj = (const float*)d_in[15];
    const float* Wl1 = (const float*)d_in[16];
    const float* bl1 = (const float*)d_in[17];
    const float* Wl2 = (const float*)d_in[18];
    const float* bl2 = (const float*)d_in[19];
    float* out = (float*)d_out;

    float *bufP0, *bufP1, *bufS0, *bufS1, *dinvP, *dinvS, *Wc, *W2;
    int *rowP, *rowS, *curP, *curS, *srcP, *srcS, *bsum;
    cudaGetSymbolAddress((void**)&bufP0, g_bufP0);
    cudaGetSymbolAddress((void**)&bufP1, g_bufP1);
    cudaGetSymbolAddress((void**)&bufS0, g_bufS0);
    cudaGetSymbolAddress((void**)&bufS1, g_bufS1);
    cudaGetSymbolAddress((void**)&dinvP, g_dinvP);
    cudaGetSymbolAddress((void**)&dinvS, g_dinvS);
    cudaGetSymbolAddress((void**)&rowP,  g_rowP);
    cudaGetSymbolAddress((void**)&rowS,  g_rowS);
    cudaGetSymbolAddress((void**)&curP,  g_curP);
    cudaGetSymbolAddress((void**)&curS,  g_curS);
    cudaGetSymbolAddress((void**)&srcP,  g_srcP);
    cudaGetSymbolAddress((void**)&srcS,  g_srcS);
    cudaGetSymbolAddress((void**)&Wc,    g_Wc);
    cudaGetSymbolAddress((void**)&W2,    g_W2);
    cudaGetSymbolAddress((void**)&bsum,  g_bsum);

    cudaFuncSetAttribute(k_prep, cudaFuncAttributeMaxDynamicSharedMemorySize, PREP_SMEM);

    if (g_s1 == nullptr) {
        cudaStreamCreateWithFlags(&g_s1, cudaStreamNonBlocking);
        cudaStreamCreateWithFlags(&g_s2, cudaStreamNonBlocking);
        cudaEventCreateWithFlags(&g_evRoot, cudaEventDisableTiming);
        cudaEventCreateWithFlags(&g_evCSR,  cudaEventDisableTiming);
        cudaEventCreateWithFlags(&g_evPrep, cudaEventDisableTiming);
        cudaEventCreateWithFlags(&g_evS,    cudaEventDisableTiming);
        cudaEventCreateWithFlags(&g_evTail, cudaEventDisableTiming);
    }
    cudaStream_t s1 = g_s1, s2 = g_s2;

    const int EP = in_sizes[2] / 2;
    const int ES = in_sizes[3] / 2;
    const int EL = in_sizes[4];
    const int nbP = cdiv(NP, 1024), nbS = cdiv(NS, 1024);

    float* W2cP = W2;
    float* b2cP = W2 + 64 * 64;
    float* W2cS = W2 + 64 * 64 + 64;
    float* b2cS = W2 + 2 * 64 * 64 + 64;

    // fork
    cudaEventRecord(g_evRoot, 0);
    cudaStreamWaitEvent(s1, g_evRoot, 0);
    cudaStreamWaitEvent(s2, g_evRoot, 0);

    // ---- s2: CSR build chain ----
    k_countB<<<cdiv(EP + ES, 256), 256, 0, s2>>>(ei_p, EP, ei_s, ES, curP, curS);
    k_scan1B<<<nbP + nbS, 1024, 0, s2>>>(curP, curS, rowP, rowS, bsum, nbP);
    k_scan2B<<<1, 1024, 0, s2>>>(bsum, nbP, nbS);
    k_scan3B<<<cdiv(NP + NS, 256), 256, 0, s2>>>(rowP, rowS, curP, curS, bsum, nbP, EP, ES, dinvP, dinvS);
    k_fillB<<<cdiv(EP + ES, 256), 256, 0, s2>>>(ei_p, EP, ei_s, ES, curP, curS, srcP, srcS);
    cudaEventRecord(g_evCSR, s2);
    k_reset<<<cdiv(NP, 256), 256, 0, s2>>>(curP, curS);
    cudaEventRecord(g_evTail, s2);

    // ---- s1: prep + substrate chain ----
    k_prep<<<1, 256, PREP_SMEM, s1>>>(Wproj, bproj, Wl1, bl1, Wp2, bp2, Ws2, bs2, Wc, W2);
    cudaEventRecord(g_evPrep, s1);
    k_gemm<<<cdiv(NS, BM), 256, 0, s1>>>(x_s, Ws1, bufS0, NS, SD);
    cudaStreamWaitEvent(s1, g_evCSR, 0);
    k_aggregate<<<cdiv(NS * 32, 256), 256, 0, s1>>>(bufS0, bufS1, rowS, srcS, dinvS, bs1, NS);
    k_gemm<<<cdiv(NS, BM), 256, 0, s1>>>(bufS1, W2cS, bufS0, NS, HF);
    k_aggregate<<<cdiv(NS * 32, 256), 256, 0, s1>>>(bufS0, bufS1, rowS, srcS, dinvS, b2cS, NS);
    cudaEventRecord(g_evS, s1);

    // ---- s0 (main): protein chain ----
    k_gemm<<<cdiv(NP, BM), 256>>>(x_p, Wp1, bufP0, NP, PD);
    cudaStreamWaitEvent(0, g_evCSR, 0);
    k_aggregate<<<cdiv(NP * 32, 256), 256>>>(bufP0, bufP1, rowP, srcP, dinvP, bp1, NP);
    cudaStreamWaitEvent(0, g_evPrep, 0);
    k_gemm<<<cdiv(NP, BM), 256>>>(bufP1, W2cP, bufP0, NP, HF);
    k_aggregate<<<cdiv(NP * 32, 256), 256>>>(bufP0, bufP1, rowP, srcP, dinvP, b2cP, NP);

    // ---- link prediction (joins S chain) ----
    cudaStreamWaitEvent(0, g_evS, 0);
    {
        long long threads = (long long)EL * 32;
        int blocks = (int)((threads + 255) / 256);
        k_link<<<blocks, 256>>>(bufP1, bufS1, ed_p, ed_s, Wc + 128 * 64, Wl2, bl2, out, EL);
    }

    // join s2 tail (reset) back into the origin stream
    cudaStreamWaitEvent(0, g_evTail, 0);
}

// round 12
// speedup vs baseline: 1.2114x; 1.0465x over previous
#include <cuda_runtime.h>
#include <cstdint>
#include <cstdio>

// ---------------- problem constants ----------------
#define NP 100000
#define NS 50000
#define PD 1024
#define SD 512
#define HF 64
#define EPN 3200000
#define ESN 1600000
#define ELN 2000000

// ---------------- device scratch (static; zero-initialized at load) ----------------
__device__ float g_bufP0[(size_t)NP * HF];
__device__ float g_bufP1[(size_t)NP * HF];
__device__ float g_bufS0[(size_t)NS * HF];
__device__ float g_bufS1[(size_t)NS * HF];
__device__ float g_dinvP[NP];
__device__ float g_dinvS[NS];
__device__ int   g_rowP[NP + 1];
__device__ int   g_rowS[NS + 1];
__device__ int   g_curP[NP];   // counts -> cursor; zero at start of each replay
__device__ int   g_curS[NS];
__device__ int   g_srcP[EPN];
__device__ int   g_srcS[ESN];
__device__ float g_Wc[128 * 64 + 64];      // Wcomb [128,64] row-major, then bcomb[64]
__device__ float g_W2[2 * (64 * 64 + 64)]; // W2cP[64x64], b2cP[64], W2cS[64x64], b2cS[64]
__device__ int   g_bsum[256];

// ================= CSR build (both graphs in shared kernels) =================
__global__ void k_countB(const int* __restrict__ eiP, int EP,
                         const int* __restrict__ eiS, int ES,
                         int* __restrict__ cntP, int* __restrict__ cntS) {
    int e = blockIdx.x * blockDim.x + threadIdx.x;
    if (e < EP) {
        atomicAdd(&cntP[eiP[EP + e]], 1);
    } else if (e < EP + ES) {
        int l = e - EP;
        atomicAdd(&cntS[eiS[ES + l]], 1);
    }
}

__global__ void k_scan1B(const int* __restrict__ cntP, const int* __restrict__ cntS,
                         int* __restrict__ rowP, int* __restrict__ rowS,
                         int* __restrict__ blockSums, int nbP) {
    __shared__ int sh[1024];
    int b = blockIdx.x;
    const int* cnt;
    int* rowOut;
    int N, local0;
    if (b < nbP) { cnt = cntP; rowOut = rowP; N = NP; local0 = b * 1024; }
    else         { cnt = cntS; rowOut = rowS; N = NS; local0 = (b - nbP) * 1024; }
    int i = local0 + threadIdx.x;
    int v = (i < N) ? cnt[i] : 0;
    sh[threadIdx.x] = v;
    __syncthreads();
    for (int off = 1; off < 1024; off <<= 1) {
        int t = 0;
        if ((int)threadIdx.x >= off) t = sh[threadIdx.x - off];
        __syncthreads();
        sh[threadIdx.x] += t;
        __syncthreads();
    }
    int incl = sh[threadIdx.x];
    if (i < N) rowOut[i] = incl - v;
    if (threadIdx.x == 1023) blockSums[b] = incl;
}

__global__ void k_scan2B(int* __restrict__ blockSums, int nbP, int nbS) {
    __shared__ int sh[1024];
    int nb = nbP + nbS;
    int t = threadIdx.x;
    int v = (t < nb) ? blockSums[t] : 0;
    sh[t] = v;
    __syncthreads();
    for (int off = 1; off < 1024; off <<= 1) {
        int x = 0;
        if (t >= off) x = sh[t - off];
        __syncthreads();
        sh[t] += x;
        __syncthreads();
    }
    int excl = sh[t] - v;
    int sumP = sh[nbP - 1];
    if (t < nbP) blockSums[t] = excl;
    else if (t < nb) blockSums[t] = excl - sumP;
}

__global__ void k_scan3B(int* __restrict__ rowP, int* __restrict__ rowS,
                         int* __restrict__ curP, int* __restrict__ curS,
                         const int* __restrict__ blockSums, int nbP,
                         int EP, int ES,
                         float* __restrict__ dinvP, float* __restrict__ dinvS) {
    int i = blockIdx.x * blockDim.x + threadIdx.x;
    if (i < NP) {
        int r = rowP[i] + blockSums[i >> 10];
        int deg = curP[i];
        rowP[i] = r;
        curP[i] = r;
        dinvP[i] = rsqrtf((float)(deg + 1));
        if (i == 0) rowP[NP] = EP;
    } else if (i < NP + NS) {
        int l = i - NP;
        int r = rowS[l] + blockSums[(l >> 10) + nbP];
        int deg = curS[l];
        rowS[l] = r;
        curS[l] = r;
        dinvS[l] = rsqrtf((float)(deg + 1));
        if (l == 0) rowS[NS] = ES;
    }
}

__global__ void k_fillB(const int* __restrict__ eiP, int EP,
                        const int* __restrict__ eiS, int ES,
                        int* __restrict__ curP, int* __restrict__ curS,
                        int* __restrict__ srcP, int* __restrict__ srcS) {
    int e = blockIdx.x * blockDim.x + threadIdx.x;
    if (e < EP) {
        int d = eiP[EP + e];
        int p = atomicAdd(&curP[d], 1);
        srcP[p] = eiP[e];
    } else if (e < EP + ES) {
        int l = e - EP;
        int d = eiS[ES + l];
        int p = atomicAdd(&curS[d], 1);
        srcS[p] = eiS[l];
    }
}

__global__ void k_reset(int* __restrict__ curP, int* __restrict__ curS) {
    int i = blockIdx.x * blockDim.x + threadIdx.x;
    if (i < NP) curP[i] = 0;
    if (i < NS) curS[i] = 0;
}

// ======== tf32 tensor-core GEMM body (round-6 proven config) ========
#define BM 128
#define BN 64
#define BK 32
#define XPAD 40
#define WPAD 72

__device__ __forceinline__ unsigned f2tf32(float f) {
    unsigned u;
    asm("cvt.rna.tf32.f32 %0, %1;" : "=r"(u) : "f"(f));
    return u;
}

__device__ __forceinline__ void gemm_body(const float* __restrict__ X,
                                          const float* __restrict__ W,
                                          float* __restrict__ Y, int M, int K,
                                          int row0, unsigned* Xs, unsigned* Ws) {
    int tid = threadIdx.x;
    int wid = tid >> 5, lane = tid & 31;
    int lq = lane >> 2;
    int lr = lane & 3;
    int rb = (wid & 3) * 32;
    int cb = (wid >> 2) * 32;
    int nt = K / BK;

    int xr[4], xc[4];
#pragma unroll
    for (int l = 0; l < 4; l++) {
        int idx = tid + l * 256;
        xr[l] = idx >> 3;
        xc[l] = idx & 7;
    }
    int wk[2], wc[2];
#pragma unroll
    for (int l = 0; l < 2; l++) {
        int idx = tid + l * 256;
        wk[l] = idx >> 4;
        wc[l] = idx & 15;
    }

    float acc[2][4][4];
#pragma unroll
    for (int mt = 0; mt < 2; mt++)
#pragma unroll
        for (int nb = 0; nb < 4; nb++)
#pragma unroll
            for (int j = 0; j < 4; j++) acc[mt][nb][j] = 0.f;

    float4 xv[4], wv[2];
#pragma unroll
    for (int l = 0; l < 4; l++) {
        int gr = row0 + xr[l];
        xv[l] = (gr < M) ? *(const float4*)(X + (size_t)gr * K + xc[l] * 4)
                         : make_float4(0.f, 0.f, 0.f, 0.f);
    }
#pragma unroll
    for (int l = 0; l < 2; l++)
        wv[l] = *(const float4*)(W + (size_t)wk[l] * HF + wc[l] * 4);
#pragma unroll
    for (int l = 0; l < 4; l++) {
        uint4 u = make_uint4(f2tf32(xv[l].x), f2tf32(xv[l].y), f2tf32(xv[l].z), f2tf32(xv[l].w));
        *(uint4*)&Xs[xr[l] * XPAD + xc[l] * 4] = u;
    }
#pragma unroll
    for (int l = 0; l < 2; l++) {
        uint4 u = make_uint4(f2tf32(wv[l].x), f2tf32(wv[l].y), f2tf32(wv[l].z), f2tf32(wv[l].w));
        *(uint4*)&Ws[wk[l] * WPAD + wc[l] * 4] = u;
    }
    __syncthreads();

    for (int t = 0; t < nt; t++) {
        if (t + 1 < nt) {
            const float* Xn = X + (size_t)(t + 1) * BK;
            const float* Wn = W + (size_t)(t + 1) * BK * HF;
#pragma unroll
            for (int l = 0; l < 4; l++) {
                int gr = row0 + xr[l];
                xv[l] = (gr < M) ? *(const float4*)(Xn + (size_t)gr * K + xc[l] * 4)
                                 : make_float4(0.f, 0.f, 0.f, 0.f);
            }
#pragma unroll
            for (int l = 0; l < 2; l++)
                wv[l] = *(const float4*)(Wn + (size_t)wk[l] * HF + wc[l] * 4);
        }

#pragma unroll
        for (int ks = 0; ks < 4; ks++) {
            int k0 = ks * 8;
            unsigned a[2][4];
#pragma unroll
            for (int mt = 0; mt < 2; mt++) {
                int r = rb + mt * 16 + lq;
                a[mt][0] = Xs[r * XPAD + k0 + lr];
                a[mt][1] = Xs[(r + 8) * XPAD + k0 + lr];
                a[mt][2] = Xs[r * XPAD + k0 + 4 + lr];
                a[mt][3] = Xs[(r + 8) * XPAD + k0 + 4 + lr];
            }
            unsigned b[4][2];
#pragma unroll
            for (int nb = 0; nb < 4; nb++) {
                int c = cb + nb * 8 + lq;
                b[nb][0] = Ws[(k0 + lr) * WPAD + c];
                b[nb][1] = Ws[(k0 + 4 + lr) * WPAD + c];
            }
#pragma unroll
            for (int mt = 0; mt < 2; mt++)
#pragma unroll
                for (int nb = 0; nb < 4; nb++)
                    asm volatile(
                        "mma.sync.aligned.m16n8k8.row.col.f32.tf32.tf32.f32 "
                        "{%0,%1,%2,%3}, {%4,%5,%6,%7}, {%8,%9}, {%0,%1,%2,%3};"
                        : "+f"(acc[mt][nb][0]), "+f"(acc[mt][nb][1]),
                          "+f"(acc[mt][nb][2]), "+f"(acc[mt][nb][3])
                        : "r"(a[mt][0]), "r"(a[mt][1]), "r"(a[mt][2]), "r"(a[mt][3]),
                          "r"(b[nb][0]), "r"(b[nb][1]));
        }
        __syncthreads();

        if (t + 1 < nt) {
#pragma unroll
            for (int l = 0; l < 4; l++) {
                uint4 u = make_uint4(f2tf32(xv[l].x), f2tf32(xv[l].y), f2tf32(xv[l].z), f2tf32(xv[l].w));
                *(uint4*)&Xs[xr[l] * XPAD + xc[l] * 4] = u;
            }
#pragma unroll
            for (int l = 0; l < 2; l++) {
                uint4 u = make_uint4(f2tf32(wv[l].x), f2tf32(wv[l].y), f2tf32(wv[l].z), f2tf32(wv[l].w));
                *(uint4*)&Ws[wk[l] * WPAD + wc[l] * 4] = u;
            }
            __syncthreads();
        }
    }

#pragma unroll
    for (int mt = 0; mt < 2; mt++) {
#pragma unroll
        for (int nb = 0; nb < 4; nb++) {
            int r = row0 + rb + mt * 16 + lq;
            int c = cb + nb * 8 + 2 * lr;
            if (r < M)
                *(float2*)(Y + (size_t)r * HF + c) = make_float2(acc[mt][nb][0], acc[mt][nb][1]);
            if (r + 8 < M)
                *(float2*)(Y + (size_t)(r + 8) * HF + c) = make_float2(acc[mt][nb][2], acc[mt][nb][3]);
        }
    }
}

// merged GEMM: blocks [0,nb0) do segment 0, rest segment 1
__global__ __launch_bounds__(256, 2) void k_gemm2(
    const float* __restrict__ X0, const float* __restrict__ W0, float* __restrict__ Y0,
    int M0, int K0, int nb0,
    const float* __restrict__ X1, const float* __restrict__ W1, float* __restrict__ Y1,
    int M1, int K1) {
    __shared__ unsigned Xs[BM * XPAD];
    __shared__ unsigned Ws[BK * WPAD];
    int b = blockIdx.x;
    if (b < nb0) gemm_body(X0, W0, Y0, M0, K0, b * BM, Xs, Ws);
    else         gemm_body(X1, W1, Y1, M1, K1, (b - nb0) * BM, Xs, Ws);
}

// ---------------- merged GCN aggregation (P + S in one launch) ----------------
__device__ __forceinline__ void agg_node(const float* __restrict__ H, float* __restrict__ OUT,
                                         const int* __restrict__ row, const int* __restrict__ srcs,
                                         const float* __restrict__ dinv, const float* __restrict__ bias,
                                         int dst, int lane) {
    float di = dinv[dst];
    const float2* Hp = (const float2*)H;
    float2 hs = Hp[(size_t)dst * 32 + lane];
    float2 acc = make_float2(hs.x * di, hs.y * di);
    int s = row[dst], e = row[dst + 1];
    int i = s;
    for (; i + 4 <= e; i += 4) {
        int i0 = srcs[i], i1 = srcs[i + 1], i2 = srcs[i + 2], i3 = srcs[i + 3];
        float d0 = dinv[i0], d1 = dinv[i1], d2 = dinv[i2], d3 = dinv[i3];
        float2 h0 = Hp[(size_t)i0 * 32 + lane];
        float2 h1 = Hp[(size_t)i1 * 32 + lane];
        float2 h2 = Hp[(size_t)i2 * 32 + lane];
        float2 h3 = Hp[(size_t)i3 * 32 + lane];
        acc.x += h0.x * d0; acc.y += h0.y * d0;
        acc.x += h1.x * d1; acc.y += h1.y * d1;
        acc.x += h2.x * d2; acc.y += h2.y * d2;
        acc.x += h3.x * d3; acc.y += h3.y * d3;
    }
    for (; i < e; i++) {
        int src = srcs[i];
        float ds = dinv[src];
        float2 h = Hp[(size_t)src * 32 + lane];
        acc.x += h.x * ds;
        acc.y += h.y * ds;
    }
    float2 b2 = ((const float2*)bias)[lane];
    float2 o = make_float2(acc.x * di + b2.x, acc.y * di + b2.y);
    ((float2*)OUT)[(size_t)dst * 32 + lane] = o;
}

__global__ void k_aggregate2(const float* __restrict__ HP, float* __restrict__ OP,
                             const int* __restrict__ rowP, const int* __restrict__ srcP,
                             const float* __restrict__ dinvP, const float* __restrict__ biasP,
                             const float* __restrict__ HS, float* __restrict__ OS,
                             const int* __restrict__ rowS, const int* __restrict__ srcS,
                             const float* __restrict__ dinvS, const float* __restrict__ biasS) {
    int warp = (blockIdx.x * blockDim.x + threadIdx.x) >> 5;
    int lane = threadIdx.x & 31;
    if (warp < NP) {
        agg_node(HP, OP, rowP, srcP, dinvP, biasP, warp, lane);
    } else if (warp < NP + NS) {
        agg_node(HS, OS, rowS, srcS, dinvS, biasS, warp - NP, lane);
    }
}

// ---- fused prep: Wc = Wproj@Wl1 (+bcomb), then W2cP/W2cS = Wp2/Ws2 @ Wc halves ----
__global__ void k_prep(const float* __restrict__ Wproj, const float* __restrict__ bproj,
                       const float* __restrict__ Wl1, const float* __restrict__ bl1,
                       const float* __restrict__ Wp2, const float* __restrict__ bp2,
                       const float* __restrict__ Ws2, const float* __restrict__ bs2,
                       float* __restrict__ Wc, float* __restrict__ W2) {
    extern __shared__ float sh[];
    float* sWl1 = sh;            // 128*64
    float* sWc  = sh + 128 * 64; // 128*64
    for (int i = threadIdx.x; i < 128 * 64; i += blockDim.x) sWl1[i] = Wl1[i];
    __syncthreads();
    for (int o = threadIdx.x; o < 128 * 64; o += blockDim.x) {
        int i = o >> 6, j = o & 63;
        float s = 0.f;
        for (int k = 0; k < 128; k++) s += Wproj[i * 128 + k] * sWl1[k * 64 + j];
        sWc[o] = s;
        Wc[o] = s;
    }
    for (int j = threadIdx.x; j < 64; j += blockDim.x) {
        float s = bl1[j];
        for (int k = 0; k < 128; k++) s += bproj[k] * sWl1[k * 64 + j];
        Wc[128 * 64 + j] = s;
    }
    __syncthreads();
    float* W2cP = W2;
    float* b2cP = W2 + 64 * 64;
    float* W2cS = W2 + 64 * 64 + 64;
    float* b2cS = W2 + 2 * 64 * 64 + 64;
    for (int o = threadIdx.x; o < 64 * 64; o += blockDim.x) {
        int i = o >> 6, j = o & 63;
        float sp = 0.f, ss = 0.f;
        for (int k = 0; k < 64; k++) {
            sp += Wp2[i * 64 + k] * sWc[k * 64 + j];
            ss += Ws2[i * 64 + k] * sWc[(64 + k) * 64 + j];
        }
        W2cP[o] = sp;
        W2cS[o] = ss;
    }
    for (int j = threadIdx.x; j < 64; j += blockDim.x) {
        float sp = 0.f, ss = 0.f;
        for (int k = 0; k < 64; k++) {
            sp += bp2[k] * sWc[k * 64 + j];
            ss += bs2[k] * sWc[(64 + k) * 64 + j];
        }
        b2cP[j] = sp;
        b2cS[j] = ss;
    }
}
#define PREP_SMEM (2 * 128 * 64 * 4)   // 64 KB

// ---------------- link predictor ----------------
__global__ void k_link(const float* __restrict__ Ap, const float* __restrict__ As,
                       const int* __restrict__ ep, const int* __restrict__ es,
                       const float* __restrict__ bc, const float* __restrict__ wl2,
                       const float* __restrict__ bl2, float* __restrict__ out, int EL) {
    int warp = (blockIdx.x * blockDim.x + threadIdx.x) >> 5;
    int lane = threadIdx.x & 31;
    if (warp >= EL) return;
    int p = ep[warp];
    int s = es[warp];
    float2 a = ((const float2*)Ap)[(size_t)p * 32 + lane];
    float2 b = ((const float2*)As)[(size_t)s * 32 + lane];
    float2 c = ((const float2*)bc)[lane];
    float hx = fmaxf(a.x + b.x + c.x, 0.f);
    float hy = fmaxf(a.y + b.y + c.y, 0.f);
    float2 w = ((const float2*)wl2)[lane];
    float part = hx * w.x + hy * w.y;
#pragma unroll
    for (int off = 16; off; off >>= 1) part += __shfl_xor_sync(0xffffffffu, part, off);
    if (lane == 0) out[warp] = part + bl2[0];
}

// ---------------- host orchestration ----------------
static inline int cdiv(int a, int b) { return (a + b - 1) / b; }

// streams/events created ONCE (pre-baseline on the correctness call) and reused.
static cudaStream_t g_s1 = nullptr, g_s2 = nullptr;
static cudaEvent_t g_evRoot, g_evCSR, g_evPrep, g_evTail;

extern "C" void kernel_launch(void* const* d_in, const int* in_sizes, int n_in,
                              void* d_out, int out_size) {
    const float* x_p  = (const float*)d_in[0];
    const float* x_s  = (const float*)d_in[1];
    const int*   ei_p = (const int*)d_in[2];
    const int*   ei_s = (const int*)d_in[3];
    const int*   ed_p = (const int*)d_in[4];
    const int*   ed_s = (const int*)d_in[5];
    const float* Wp1 = (const float*)d_in[6];
    const float* bp1 = (const float*)d_in[7];
    const float* Ws1 = (const float*)d_in[8];
    const float* bs1 = (const float*)d_in[9];
    const float* Wp2 = (const float*)d_in[10];
    const float* bp2 = (const float*)d_in[11];
    const float* Ws2 = (const float*)d_in[12];
    const float* bs2 = (const float*)d_in[13];
    const float* Wproj = (const float*)d_in[14];
    const float* bproj = (const float*)d_in[15];
    const float* Wl1 = (const float*)d_in[16];
    const float* bl1 = (const float*)d_in[17];
    const float* Wl2 = (const float*)d_in[18];
    const float* bl2 = (const float*)d_in[19];
    float* out = (float*)d_out;

    float *bufP0, *bufP1, *bufS0, *bufS1, *dinvP, *dinvS, *Wc, *W2;
    int *rowP, *rowS, *curP, *curS, *srcP, *srcS, *bsum;
    cudaGetSymbolAddress((void**)&bufP0, g_bufP0);
    cudaGetSymbolAddress((void**)&bufP1, g_bufP1);
    cudaGetSymbolAddress((void**)&bufS0, g_bufS0);
    cudaGetSymbolAddress((void**)&bufS1, g_bufS1);
    cudaGetSymbolAddress((void**)&dinvP, g_dinvP);
    cudaGetSymbolAddress((void**)&dinvS, g_dinvS);
    cudaGetSymbolAddress((void**)&rowP,  g_rowP);
    cudaGetSymbolAddress((void**)&rowS,  g_rowS);
    cudaGetSymbolAddress((void**)&curP,  g_curP);
    cudaGetSymbolAddress((void**)&curS,  g_curS);
    cudaGetSymbolAddress((void**)&srcP,  g_srcP);
    cudaGetSymbolAddress((void**)&srcS,  g_srcS);
    cudaGetSymbolAddress((void**)&Wc,    g_Wc);
    cudaGetSymbolAddress((void**)&W2,    g_W2);
    cudaGetSymbolAddress((void**)&bsum,  g_bsum);

    cudaFuncSetAttribute(k_prep, cudaFuncAttributeMaxDynamicSharedMemorySize, PREP_SMEM);

    if (g_s1 == nullptr) {
        cudaStreamCreateWithFlags(&g_s1, cudaStreamNonBlocking);
        cudaStreamCreateWithFlags(&g_s2, cudaStreamNonBlocking);
        cudaEventCreateWithFlags(&g_evRoot, cudaEventDisableTiming);
        cudaEventCreateWithFlags(&g_evCSR,  cudaEventDisableTiming);
        cudaEventCreateWithFlags(&g_evPrep, cudaEventDisableTiming);
        cudaEventCreateWithFlags(&g_evTail, cudaEventDisableTiming);
    }
    cudaStream_t s1 = g_s1, s2 = g_s2;

    const int EP = in_sizes[2] / 2;
    const int ES = in_sizes[3] / 2;
    const int EL = in_sizes[4];
    const int nbP = cdiv(NP, 1024), nbS = cdiv(NS, 1024);
    const int gP = cdiv(NP, BM), gS = cdiv(NS, BM);          // 782, 391
    const int aggBlocks = cdiv((NP + NS) * 32, 256);         // 18750

    float* W2cP = W2;
    float* b2cP = W2 + 64 * 64;
    float* W2cS = W2 + 64 * 64 + 64;
    float* b2cS = W2 + 2 * 64 * 64 + 64;

    // fork
    cudaEventRecord(g_evRoot, 0);
    cudaStreamWaitEvent(s1, g_evRoot, 0);
    cudaStreamWaitEvent(s2, g_evRoot, 0);

    // ---- s2: CSR build chain ----
    k_countB<<<cdiv(EP + ES, 256), 256, 0, s2>>>(ei_p, EP, ei_s, ES, curP, curS);
    k_scan1B<<<nbP + nbS, 1024, 0, s2>>>(curP, curS, rowP, rowS, bsum, nbP);
    k_scan2B<<<1, 1024, 0, s2>>>(bsum, nbP, nbS);
    k_scan3B<<<cdiv(NP + NS, 256), 256, 0, s2>>>(rowP, rowS, curP, curS, bsum, nbP, EP, ES, dinvP, dinvS);
    k_fillB<<<cdiv(EP + ES, 256), 256, 0, s2>>>(ei_p, EP, ei_s, ES, curP, curS, srcP, srcS);
    cudaEventRecord(g_evCSR, s2);
    k_reset<<<cdiv(NP, 256), 256, 0, s2>>>(curP, curS);
    cudaEventRecord(g_evTail, s2);

    // ---- s1: prep ----
    k_prep<<<1, 256, PREP_SMEM, s1>>>(Wproj, bproj, Wl1, bl1, Wp2, bp2, Ws2, bs2, Wc, W2);
    cudaEventRecord(g_evPrep, s1);

    // ---- s0 (main): merged P+S chain ----
    k_gemm2<<<gP + gS, 256>>>(x_p, Wp1, bufP0, NP, PD, gP,
                              x_s, Ws1, bufS0, NS, SD);
    cudaStreamWaitEvent(0, g_evCSR, 0);
    k_aggregate2<<<aggBlocks, 256>>>(bufP0, bufP1, rowP, srcP, dinvP, bp1,
                                     bufS0, bufS1, rowS, srcS, dinvS, bs1);
    cudaStreamWaitEvent(0, g_evPrep, 0);
    k_gemm2<<<gP + gS, 256>>>(bufP1, W2cP, bufP0, NP, HF, gP,
                              bufS1, W2cS, bufS0, NS, HF);
    k_aggregate2<<<aggBlocks, 256>>>(bufP0, bufP1, rowP, srcP, dinvP, b2cP,
                                     bufS0, bufS1, rowS, srcS, dinvS, b2cS);

    // ---- link prediction ----
    {
        long long threads = (long long)EL * 32;
        int blocks = (int)((threads + 255) / 256);
        k_link<<<blocks, 256>>>(bufP1, bufS1, ed_p, ed_s, Wc + 128 * 64, Wl2, bl2, out, EL);
    }

    // join s2 tail (reset) back into the origin stream
    cudaStreamWaitEvent(0, g_evTail, 0);
}

// round 13
// speedup vs baseline: 1.2284x; 1.0141x over previous
#include <cuda_runtime.h>
#include <cstdint>
#include <cstdio>

// ---------------- problem constants ----------------
#define NP 100000
#define NS 50000
#define PD 1024
#define SD 512
#define HF 64
#define EPN 3200000
#define ESN 1600000
#define ELN 2000000

// ---------------- device scratch (static; zero-initialized at load) ----------------
__device__ float g_bufP0[(size_t)NP * HF];
__device__ float g_bufP1[(size_t)NP * HF];
__device__ float g_bufS0[(size_t)NS * HF];
__device__ float g_bufS1[(size_t)NS * HF];
__device__ float g_dinvP[NP];
__device__ float g_dinvS[NS];
__device__ int   g_rowP[NP + 1];
__device__ int   g_rowS[NS + 1];
__device__ int   g_curP[NP];   // counts -> cursor; zero at start of each replay
__device__ int   g_curS[NS];
__device__ int   g_srcP[EPN];
__device__ int   g_srcS[ESN];
__device__ float g_Wc[128 * 64 + 64];      // Wcomb [128,64] row-major, then bcomb[64]
__device__ float g_W2[2 * (64 * 64 + 64)]; // W2cP[64x64], b2cP[64], W2cS[64x64], b2cS[64]
__device__ int   g_bsum[256];

// ================= CSR build (both graphs in shared kernels) =================
__global__ void k_countB(const int* __restrict__ eiP, int EP,
                         const int* __restrict__ eiS, int ES,
                         int* __restrict__ cntP, int* __restrict__ cntS) {
    int e = blockIdx.x * blockDim.x + threadIdx.x;
    if (e < EP) {
        atomicAdd(&cntP[eiP[EP + e]], 1);
    } else if (e < EP + ES) {
        int l = e - EP;
        atomicAdd(&cntS[eiS[ES + l]], 1);
    }
}

__global__ void k_scan1B(const int* __restrict__ cntP, const int* __restrict__ cntS,
                         int* __restrict__ rowP, int* __restrict__ rowS,
                         int* __restrict__ blockSums, int nbP) {
    __shared__ int sh[1024];
    int b = blockIdx.x;
    const int* cnt;
    int* rowOut;
    int N, local0;
    if (b < nbP) { cnt = cntP; rowOut = rowP; N = NP; local0 = b * 1024; }
    else         { cnt = cntS; rowOut = rowS; N = NS; local0 = (b - nbP) * 1024; }
    int i = local0 + threadIdx.x;
    int v = (i < N) ? cnt[i] : 0;
    sh[threadIdx.x] = v;
    __syncthreads();
    for (int off = 1; off < 1024; off <<= 1) {
        int t = 0;
        if ((int)threadIdx.x >= off) t = sh[threadIdx.x - off];
        __syncthreads();
        sh[threadIdx.x] += t;
        __syncthreads();
    }
    int incl = sh[threadIdx.x];
    if (i < N) rowOut[i] = incl - v;
    if (threadIdx.x == 1023) blockSums[b] = incl;
}

__global__ void k_scan2B(int* __restrict__ blockSums, int nbP, int nbS) {
    __shared__ int sh[1024];
    int nb = nbP + nbS;
    int t = threadIdx.x;
    int v = (t < nb) ? blockSums[t] : 0;
    sh[t] = v;
    __syncthreads();
    for (int off = 1; off < 1024; off <<= 1) {
        int x = 0;
        if (t >= off) x = sh[t - off];
        __syncthreads();
        sh[t] += x;
        __syncthreads();
    }
    int excl = sh[t] - v;
    int sumP = sh[nbP - 1];
    if (t < nbP) blockSums[t] = excl;
    else if (t < nb) blockSums[t] = excl - sumP;
}

__global__ void k_scan3B(int* __restrict__ rowP, int* __restrict__ rowS,
                         int* __restrict__ curP, int* __restrict__ curS,
                         const int* __restrict__ blockSums, int nbP,
                         int EP, int ES,
                         float* __restrict__ dinvP, float* __restrict__ dinvS) {
    int i = blockIdx.x * blockDim.x + threadIdx.x;
    if (i < NP) {
        int r = rowP[i] + blockSums[i >> 10];
        int deg = curP[i];
        rowP[i] = r;
        curP[i] = r;
        dinvP[i] = rsqrtf((float)(deg + 1));
        if (i == 0) rowP[NP] = EP;
    } else if (i < NP + NS) {
        int l = i - NP;
        int r = rowS[l] + blockSums[(l >> 10) + nbP];
        int deg = curS[l];
        rowS[l] = r;
        curS[l] = r;
        dinvS[l] = rsqrtf((float)(deg + 1));
        if (l == 0) rowS[NS] = ES;
    }
}

__global__ void k_fillB(const int* __restrict__ eiP, int EP,
                        const int* __restrict__ eiS, int ES,
                        int* __restrict__ curP, int* __restrict__ curS,
                        int* __restrict__ srcP, int* __restrict__ srcS) {
    int e = blockIdx.x * blockDim.x + threadIdx.x;
    if (e < EP) {
        int d = eiP[EP + e];
        int p = atomicAdd(&curP[d], 1);
        srcP[p] = eiP[e];
    } else if (e < EP + ES) {
        int l = e - EP;
        int d = eiS[ES + l];
        int p = atomicAdd(&curS[d], 1);
        srcS[p] = eiS[l];
    }
}

__global__ void k_reset(int* __restrict__ curP, int* __restrict__ curS) {
    int i = blockIdx.x * blockDim.x + threadIdx.x;
    if (i < NP) curP[i] = 0;
    if (i < NS) curS[i] = 0;
}

// ======== tf32 tensor-core GEMM body (round-6 proven config) ========
#define BM 128
#define BN 64
#define BK 32
#define XPAD 40
#define WPAD 72

__device__ __forceinline__ unsigned f2tf32(float f) {
    unsigned u;
    asm("cvt.rna.tf32.f32 %0, %1;" : "=r"(u) : "f"(f));
    return u;
}

__device__ __forceinline__ void gemm_body(const float* __restrict__ X,
                                          const float* __restrict__ W,
                                          float* __restrict__ Y, int M, int K,
                                          int row0, unsigned* Xs, unsigned* Ws) {
    int tid = threadIdx.x;
    int wid = tid >> 5, lane = tid & 31;
    int lq = lane >> 2;
    int lr = lane & 3;
    int rb = (wid & 3) * 32;
    int cb = (wid >> 2) * 32;
    int nt = K / BK;

    int xr[4], xc[4];
#pragma unroll
    for (int l = 0; l < 4; l++) {
        int idx = tid + l * 256;
        xr[l] = idx >> 3;
        xc[l] = idx & 7;
    }
    int wk[2], wc[2];
#pragma unroll
    for (int l = 0; l < 2; l++) {
        int idx = tid + l * 256;
        wk[l] = idx >> 4;
        wc[l] = idx & 15;
    }

    float acc[2][4][4];
#pragma unroll
    for (int mt = 0; mt < 2; mt++)
#pragma unroll
        for (int nb = 0; nb < 4; nb++)
#pragma unroll
            for (int j = 0; j < 4; j++) acc[mt][nb][j] = 0.f;

    float4 xv[4], wv[2];
#pragma unroll
    for (int l = 0; l < 4; l++) {
        int gr = row0 + xr[l];
        xv[l] = (gr < M) ? *(const float4*)(X + (size_t)gr * K + xc[l] * 4)
                         : make_float4(0.f, 0.f, 0.f, 0.f);
    }
#pragma unroll
    for (int l = 0; l < 2; l++)
        wv[l] = *(const float4*)(W + (size_t)wk[l] * HF + wc[l] * 4);
#pragma unroll
    for (int l = 0; l < 4; l++) {
        uint4 u = make_uint4(f2tf32(xv[l].x), f2tf32(xv[l].y), f2tf32(xv[l].z), f2tf32(xv[l].w));
        *(uint4*)&Xs[xr[l] * XPAD + xc[l] * 4] = u;
    }
#pragma unroll
    for (int l = 0; l < 2; l++) {
        uint4 u = make_uint4(f2tf32(wv[l].x), f2tf32(wv[l].y), f2tf32(wv[l].z), f2tf32(wv[l].w));
        *(uint4*)&Ws[wk[l] * WPAD + wc[l] * 4] = u;
    }
    __syncthreads();

    for (int t = 0; t < nt; t++) {
        if (t + 1 < nt) {
            const float* Xn = X + (size_t)(t + 1) * BK;
            const float* Wn = W + (size_t)(t + 1) * BK * HF;
#pragma unroll
            for (int l = 0; l < 4; l++) {
                int gr = row0 + xr[l];
                xv[l] = (gr < M) ? *(const float4*)(Xn + (size_t)gr * K + xc[l] * 4)
                                 : make_float4(0.f, 0.f, 0.f, 0.f);
            }
#pragma unroll
            for (int l = 0; l < 2; l++)
                wv[l] = *(const float4*)(Wn + (size_t)wk[l] * HF + wc[l] * 4);
        }

#pragma unroll
        for (int ks = 0; ks < 4; ks++) {
            int k0 = ks * 8;
            unsigned a[2][4];
#pragma unroll
            for (int mt = 0; mt < 2; mt++) {
                int r = rb + mt * 16 + lq;
                a[mt][0] = Xs[r * XPAD + k0 + lr];
                a[mt][1] = Xs[(r + 8) * XPAD + k0 + lr];
                a[mt][2] = Xs[r * XPAD + k0 + 4 + lr];
                a[mt][3] = Xs[(r + 8) * XPAD + k0 + 4 + lr];
            }
            unsigned b[4][2];
#pragma unroll
            for (int nb = 0; nb < 4; nb++) {
                int c = cb + nb * 8 + lq;
                b[nb][0] = Ws[(k0 + lr) * WPAD + c];
                b[nb][1] = Ws[(k0 + 4 + lr) * WPAD + c];
            }
#pragma unroll
            for (int mt = 0; mt < 2; mt++)
#pragma unroll
                for (int nb = 0; nb < 4; nb++)
                    asm volatile(
                        "mma.sync.aligned.m16n8k8.row.col.f32.tf32.tf32.f32 "
                        "{%0,%1,%2,%3}, {%4,%5,%6,%7}, {%8,%9}, {%0,%1,%2,%3};"
                        : "+f"(acc[mt][nb][0]), "+f"(acc[mt][nb][1]),
                          "+f"(acc[mt][nb][2]), "+f"(acc[mt][nb][3])
                        : "r"(a[mt][0]), "r"(a[mt][1]), "r"(a[mt][2]), "r"(a[mt][3]),
                          "r"(b[nb][0]), "r"(b[nb][1]));
        }
        __syncthreads();

        if (t + 1 < nt) {
#pragma unroll
            for (int l = 0; l < 4; l++) {
                uint4 u = make_uint4(f2tf32(xv[l].x), f2tf32(xv[l].y), f2tf32(xv[l].z), f2tf32(xv[l].w));
                *(uint4*)&Xs[xr[l] * XPAD + xc[l] * 4] = u;
            }
#pragma unroll
            for (int l = 0; l < 2; l++) {
                uint4 u = make_uint4(f2tf32(wv[l].x), f2tf32(wv[l].y), f2tf32(wv[l].z), f2tf32(wv[l].w));
                *(uint4*)&Ws[wk[l] * WPAD + wc[l] * 4] = u;
            }
            __syncthreads();
        }
    }

#pragma unroll
    for (int mt = 0; mt < 2; mt++) {
#pragma unroll
        for (int nb = 0; nb < 4; nb++) {
            int r = row0 + rb + mt * 16 + lq;
            int c = cb + nb * 8 + 2 * lr;
            if (r < M)
                *(float2*)(Y + (size_t)r * HF + c) = make_float2(acc[mt][nb][0], acc[mt][nb][1]);
            if (r + 8 < M)
                *(float2*)(Y + (size_t)(r + 8) * HF + c) = make_float2(acc[mt][nb][2], acc[mt][nb][3]);
        }
    }
}

// merged GEMM: blocks [0,nb0) do segment 0, rest segment 1
__global__ __launch_bounds__(256, 2) void k_gemm2(
    const float* __restrict__ X0, const float* __restrict__ W0, float* __restrict__ Y0,
    int M0, int K0, int nb0,
    const float* __restrict__ X1, const float* __restrict__ W1, float* __restrict__ Y1,
    int M1, int K1) {
    __shared__ unsigned Xs[BM * XPAD];
    __shared__ unsigned Ws[BK * WPAD];
    int b = blockIdx.x;
    if (b < nb0) gemm_body(X0, W0, Y0, M0, K0, b * BM, Xs, Ws);
    else         gemm_body(X1, W1, Y1, M1, K1, (b - nb0) * BM, Xs, Ws);
}

// ---------------- merged GCN aggregation (P + S, 16-lane rows, 2 edges/iter) ----------------
__device__ __forceinline__ void agg_node(const float* __restrict__ H, float* __restrict__ OUT,
                                         const int* __restrict__ row, const int* __restrict__ srcs,
                                         const float* __restrict__ dinv, const float* __restrict__ bias,
                                         int dst, int lane) {
    int half = lane >> 4;     // 0: even edges, 1: odd edges
    int hl = lane & 15;       // float4 index within 64-float row
    const float4* Hp = (const float4*)H;
    float4 a0 = make_float4(0.f, 0.f, 0.f, 0.f);
    float4 a1 = make_float4(0.f, 0.f, 0.f, 0.f);
    int s = row[dst], e = row[dst + 1];
    int i = s;
    // main loop: 4 edges per iteration (2 per half), 2 independent loads per lane
    for (; i + 4 <= e; i += 4) {
        int s0 = srcs[i + half];
        int s1 = srcs[i + 2 + half];
        float d0 = dinv[s0];
        float d1 = dinv[s1];
        float4 h0 = Hp[(size_t)s0 * 16 + hl];
        float4 h1 = Hp[(size_t)s1 * 16 + hl];
        a0.x += h0.x * d0; a0.y += h0.y * d0; a0.z += h0.z * d0; a0.w += h0.w * d0;
        a1.x += h1.x * d1; a1.y += h1.y * d1; a1.z += h1.z * d1; a1.w += h1.w * d1;
    }
    // remainder: 0..3 edges
    for (; i < e; i += 2) {
        int idx = i + half;
        if (idx < e) {
            int src = srcs[idx];
            float d = dinv[src];
            float4 h = Hp[(size_t)src * 16 + hl];
            a0.x += h.x * d; a0.y += h.y * d; a0.z += h.z * d; a0.w += h.w * d;
        }
    }
    float4 acc = make_float4(a0.x + a1.x, a0.y + a1.y, a0.z + a1.z, a0.w + a1.w);
    // combine halves into lanes 0-15
    acc.x += __shfl_down_sync(0xffffffffu, acc.x, 16);
    acc.y += __shfl_down_sync(0xffffffffu, acc.y, 16);
    acc.z += __shfl_down_sync(0xffffffffu, acc.z, 16);
    acc.w += __shfl_down_sync(0xffffffffu, acc.w, 16);
    if (half == 0) {
        float di = dinv[dst];
        float4 hs = Hp[(size_t)dst * 16 + hl];   // self-loop term
        float4 b4 = ((const float4*)bias)[hl];
        float4 o;
        o.x = (acc.x + hs.x * di) * di + b4.x;
        o.y = (acc.y + hs.y * di) * di + b4.y;
        o.z = (acc.z + hs.z * di) * di + b4.z;
        o.w = (acc.w + hs.w * di) * di + b4.w;
        ((float4*)OUT)[(size_t)dst * 16 + hl] = o;
    }
}

__global__ void k_aggregate2(const float* __restrict__ HP, float* __restrict__ OP,
                             const int* __restrict__ rowP, const int* __restrict__ srcP,
                             const float* __restrict__ dinvP, const float* __restrict__ biasP,
                             const float* __restrict__ HS, float* __restrict__ OS,
                             const int* __restrict__ rowS, const int* __restrict__ srcS,
                             const float* __restrict__ dinvS, const float* __restrict__ biasS) {
    int warp = (blockIdx.x * blockDim.x + threadIdx.x) >> 5;
    int lane = threadIdx.x & 31;
    if (warp < NP) {
        agg_node(HP, OP, rowP, srcP, dinvP, biasP, warp, lane);
    } else if (warp < NP + NS) {
        agg_node(HS, OS, rowS, srcS, dinvS, biasS, warp - NP, lane);
    }
}

// ---- fused prep: Wc = Wproj@Wl1 (+bcomb), then W2cP/W2cS = Wp2/Ws2 @ Wc halves ----
__global__ void k_prep(const float* __restrict__ Wproj, const float* __restrict__ bproj,
                       const float* __restrict__ Wl1, const float* __restrict__ bl1,
                       const float* __restrict__ Wp2, const float* __restrict__ bp2,
                       const float* __restrict__ Ws2, const float* __restrict__ bs2,
                       float* __restrict__ Wc, float* __restrict__ W2) {
    extern __shared__ float sh[];
    float* sWl1 = sh;            // 128*64
    float* sWc  = sh + 128 * 64; // 128*64
    for (int i = threadIdx.x; i < 128 * 64; i += blockDim.x) sWl1[i] = Wl1[i];
    __syncthreads();
    for (int o = threadIdx.x; o < 128 * 64; o += blockDim.x) {
        int i = o >> 6, j = o & 63;
        float s = 0.f;
        for (int k = 0; k < 128; k++) s += Wproj[i * 128 + k] * sWl1[k * 64 + j];
        sWc[o] = s;
        Wc[o] = s;
    }
    for (int j = threadIdx.x; j < 64; j += blockDim.x) {
        float s = bl1[j];
        for (int k = 0; k < 128; k++) s += bproj[k] * sWl1[k * 64 + j];
        Wc[128 * 64 + j] = s;
    }
    __syncthreads();
    float* W2cP = W2;
    float* b2cP = W2 + 64 * 64;
    float* W2cS = W2 + 64 * 64 + 64;
    float* b2cS = W2 + 2 * 64 * 64 + 64;
    for (int o = threadIdx.x; o < 64 * 64; o += blockDim.x) {
        int i = o >> 6, j = o & 63;
        float sp = 0.f, ss = 0.f;
        for (int k = 0; k < 64; k++) {
            sp += Wp2[i * 64 + k] * sWc[k * 64 + j];
            ss += Ws2[i * 64 + k] * sWc[(64 + k) * 64 + j];
        }
        W2cP[o] = sp;
        W2cS[o] = ss;
    }
    for (int j = threadIdx.x; j < 64; j += blockDim.x) {
        float sp = 0.f, ss = 0.f;
        for (int k = 0; k < 64; k++) {
            sp += bp2[k] * sWc[k * 64 + j];
            ss += bs2[k] * sWc[(64 + k) * 64 + j];
        }
        b2cP[j] = sp;
        b2cS[j] = ss;
    }
}
#define PREP_SMEM (2 * 128 * 64 * 4)   // 64 KB

// ---------------- link predictor ----------------
__global__ void k_link(const float* __restrict__ Ap, const float* __restrict__ As,
                       const int* __restrict__ ep, const int* __restrict__ es,
                       const float* __restrict__ bc, const float* __restrict__ wl2,
                       const float* __restrict__ bl2, float* __restrict__ out, int EL) {
    int warp = (blockIdx.x * blockDim.x + threadIdx.x) >> 5;
    int lane = threadIdx.x & 31;
    if (warp >= EL) return;
    int p = ep[warp];
    int s = es[warp];
    float2 a = ((const float2*)Ap)[(size_t)p * 32 + lane];
    float2 b = ((const float2*)As)[(size_t)s * 32 + lane];
    float2 c = ((const float2*)bc)[lane];
    float hx = fmaxf(a.x + b.x + c.x, 0.f);
    float hy = fmaxf(a.y + b.y + c.y, 0.f);
    float2 w = ((const float2*)wl2)[lane];
    float part = hx * w.x + hy * w.y;
#pragma unroll
    for (int off = 16; off; off >>= 1) part += __shfl_xor_sync(0xffffffffu, part, off);
    if (lane == 0) out[warp] = part + bl2[0];
}

// ---------------- host orchestration ----------------
static inline int cdiv(int a, int b) { return (a + b - 1) / b; }

// streams/events created ONCE (pre-baseline on the correctness call) and reused.
static cudaStream_t g_s1 = nullptr, g_s2 = nullptr;
static cudaEvent_t g_evRoot, g_evCSR, g_evPrep, g_evTail;

extern "C" void kernel_launch(void* const* d_in, const int* in_sizes, int n_in,
                              void* d_out, int out_size) {
    const float* x_p  = (const float*)d_in[0];
    const float* x_s  = (const float*)d_in[1];
    const int*   ei_p = (const int*)d_in[2];
    const int*   ei_s = (const int*)d_in[3];
    const int*   ed_p = (const int*)d_in[4];
    const int*   ed_s = (const int*)d_in[5];
    const float* Wp1 = (const float*)d_in[6];
    const float* bp1 = (const float*)d_in[7];
    const float* Ws1 = (const float*)d_in[8];
    const float* bs1 = (const float*)d_in[9];
    const float* Wp2 = (const float*)d_in[10];
    const float* bp2 = (const float*)d_in[11];
    const float* Ws2 = (const float*)d_in[12];
    const float* bs2 = (const float*)d_in[13];
    const float* Wproj = (const float*)d_in[14];
    const float* bproj = (const float*)d_in[15];
    const float* Wl1 = (const float*)d_in[16];
    const float* bl1 = (const float*)d_in[17];
    const float* Wl2 = (const float*)d_in[18];
    const float* bl2 = (const float*)d_in[19];
    float* out = (float*)d_out;

    float *bufP0, *bufP1, *bufS0, *bufS1, *dinvP, *dinvS, *Wc, *W2;
    int *rowP, *rowS, *curP, *curS, *srcP, *srcS, *bsum;
    cudaGetSymbolAddress((void**)&bufP0, g_bufP0);
    cudaGetSymbolAddress((void**)&bufP1, g_bufP1);
    cudaGetSymbolAddress((void**)&bufS0, g_bufS0);
    cudaGetSymbolAddress((void**)&bufS1, g_bufS1);
    cudaGetSymbolAddress((void**)&dinvP, g_dinvP);
    cudaGetSymbolAddress((void**)&dinvS, g_dinvS);
    cudaGetSymbolAddress((void**)&rowP,  g_rowP);
    cudaGetSymbolAddress((void**)&rowS,  g_rowS);
    cudaGetSymbolAddress((void**)&curP,  g_curP);
    cudaGetSymbolAddress((void**)&curS,  g_curS);
    cudaGetSymbolAddress((void**)&srcP,  g_srcP);
    cudaGetSymbolAddress((void**)&srcS,  g_srcS);
    cudaGetSymbolAddress((void**)&Wc,    g_Wc);
    cudaGetSymbolAddress((void**)&W2,    g_W2);
    cudaGetSymbolAddress((void**)&bsum,  g_bsum);

    cudaFuncSetAttribute(k_prep, cudaFuncAttributeMaxDynamicSharedMemorySize, PREP_SMEM);

    if (g_s1 == nullptr) {
        cudaStreamCreateWithFlags(&g_s1, cudaStreamNonBlocking);
        cudaStreamCreateWithFlags(&g_s2, cudaStreamNonBlocking);
        cudaEventCreateWithFlags(&g_evRoot, cudaEventDisableTiming);
        cudaEventCreateWithFlags(&g_evCSR,  cudaEventDisableTiming);
        cudaEventCreateWithFlags(&g_evPrep, cudaEventDisableTiming);
        cudaEventCreateWithFlags(&g_evTail, cudaEventDisableTiming);
    }
    cudaStream_t s1 = g_s1, s2 = g_s2;

    const int EP = in_sizes[2] / 2;
    const int ES = in_sizes[3] / 2;
    const int EL = in_sizes[4];
    const int nbP = cdiv(NP, 1024), nbS = cdiv(NS, 1024);
    const int gP = cdiv(NP, BM), gS = cdiv(NS, BM);
    const int aggBlocks = cdiv((NP + NS) * 32, 256);

    float* W2cP = W2;
    float* b2cP = W2 + 64 * 64;
    float* W2cS = W2 + 64 * 64 + 64;
    float* b2cS = W2 + 2 * 64 * 64 + 64;

    // fork
    cudaEventRecord(g_evRoot, 0);
    cudaStreamWaitEvent(s1, g_evRoot, 0);
    cudaStreamWaitEvent(s2, g_evRoot, 0);

    // ---- s2: CSR build chain ----
    k_countB<<<cdiv(EP + ES, 256), 256, 0, s2>>>(ei_p, EP, ei_s, ES, curP, curS);
    k_scan1B<<<nbP + nbS, 1024, 0, s2>>>(curP, curS, rowP, rowS, bsum, nbP);
    k_scan2B<<<1, 1024, 0, s2>>>(bsum, nbP, nbS);
    k_scan3B<<<cdiv(NP + NS, 256), 256, 0, s2>>>(rowP, rowS, curP, curS, bsum, nbP, EP, ES, dinvP, dinvS);
    k_fillB<<<cdiv(EP + ES, 256), 256, 0, s2>>>(ei_p, EP, ei_s, ES, curP, curS, srcP, srcS);
    cudaEventRecord(g_evCSR, s2);
    k_reset<<<cdiv(NP, 256), 256, 0, s2>>>(curP, curS);
    cudaEventRecord(g_evTail, s2);

    // ---- s1: prep ----
    k_prep<<<1, 256, PREP_SMEM, s1>>>(Wproj, bproj, Wl1, bl1, Wp2, bp2, Ws2, bs2, Wc, W2);
    cudaEventRecord(g_evPrep, s1);

    // ---- s0 (main): merged P+S chain ----
    k_gemm2<<<gP + gS, 256>>>(x_p, Wp1, bufP0, NP, PD, gP,
                              x_s, Ws1, bufS0, NS, SD);
    cudaStreamWaitEvent(0, g_evCSR, 0);
    k_aggregate2<<<aggBlocks, 256>>>(bufP0, bufP1, rowP, srcP, dinvP, bp1,
                                     bufS0, bufS1, rowS, srcS, dinvS, bs1);
    cudaStreamWaitEvent(0, g_evPrep, 0);
    k_gemm2<<<gP + gS, 256>>>(bufP1, W2cP, bufP0, NP, HF, gP,
                              bufS1, W2cS, bufS0, NS, HF);
    k_aggregate2<<<aggBlocks, 256>>>(bufP0, bufP1, rowP, srcP, dinvP, b2cP,
                                     bufS0, bufS1, rowS, srcS, dinvS, b2cS);

    // ---- link prediction ----
    {
        long long threads = (long long)EL * 32;
        int blocks = (int)((threads + 255) / 256);
        k_link<<<blocks, 256>>>(bufP1, bufS1, ed_p, ed_s, Wc + 128 * 64, Wl2, bl2, out, EL);
    }

    // join s2 tail (reset) back into the origin stream
    cudaStreamWaitEvent(0, g_evTail, 0);
}

// round 14
// speedup vs baseline: 1.4497x; 1.1801x over previous
#include <cuda_runtime.h>
#include <cuda_fp16.h>
#include <cstdint>
#include <cstdio>

// ---------------- problem constants ----------------
#define NP 100000
#define NS 50000
#define PD 1024
#define SD 512
#define HF 64
#define EPN 3200000
#define ESN 1600000
#define ELN 2000000

// ---------------- device scratch (static; zero-initialized at load) ----------------
__device__ float g_bufP0[(size_t)NP * HF];
__device__ float g_bufP1[(size_t)NP * HF];
__device__ float g_bufS0[(size_t)NS * HF];
__device__ float g_bufS1[(size_t)NS * HF];
__device__ float g_dinvP[NP];
__device__ float g_dinvS[NS];
__device__ int   g_rowP[NP + 1];
__device__ int   g_rowS[NS + 1];
__device__ int   g_curP[NP];   // counts -> cursor; zero at start of each replay
__device__ int   g_curS[NS];
__device__ int   g_srcP[EPN];
__device__ int   g_srcS[ESN];
__device__ float g_Wc[128 * 64 + 64];      // Wcomb [128,64] row-major, then bcomb[64]
__device__ float g_W2[2 * (64 * 64 + 64)]; // W2cP[64x64], b2cP[64], W2cS[64x64], b2cS[64]
__device__ int   g_bsum[256];

// ================= CSR build (both graphs in shared kernels) =================
__global__ void k_countB(const int* __restrict__ eiP, int EP,
                         const int* __restrict__ eiS, int ES,
                         int* __restrict__ cntP, int* __restrict__ cntS) {
    int e = blockIdx.x * blockDim.x + threadIdx.x;
    if (e < EP) {
        atomicAdd(&cntP[eiP[EP + e]], 1);
    } else if (e < EP + ES) {
        int l = e - EP;
        atomicAdd(&cntS[eiS[ES + l]], 1);
    }
}

__global__ void k_scan1B(const int* __restrict__ cntP, const int* __restrict__ cntS,
                         int* __restrict__ rowP, int* __restrict__ rowS,
                         int* __restrict__ blockSums, int nbP) {
    __shared__ int sh[1024];
    int b = blockIdx.x;
    const int* cnt;
    int* rowOut;
    int N, local0;
    if (b < nbP) { cnt = cntP; rowOut = rowP; N = NP; local0 = b * 1024; }
    else         { cnt = cntS; rowOut = rowS; N = NS; local0 = (b - nbP) * 1024; }
    int i = local0 + threadIdx.x;
    int v = (i < N) ? cnt[i] : 0;
    sh[threadIdx.x] = v;
    __syncthreads();
    for (int off = 1; off < 1024; off <<= 1) {
        int t = 0;
        if ((int)threadIdx.x >= off) t = sh[threadIdx.x - off];
        __syncthreads();
        sh[threadIdx.x] += t;
        __syncthreads();
    }
    int incl = sh[threadIdx.x];
    if (i < N) rowOut[i] = incl - v;
    if (threadIdx.x == 1023) blockSums[b] = incl;
}

__global__ void k_scan2B(int* __restrict__ blockSums, int nbP, int nbS) {
    __shared__ int sh[1024];
    int nb = nbP + nbS;
    int t = threadIdx.x;
    int v = (t < nb) ? blockSums[t] : 0;
    sh[t] = v;
    __syncthreads();
    for (int off = 1; off < 1024; off <<= 1) {
        int x = 0;
        if (t >= off) x = sh[t - off];
        __syncthreads();
        sh[t] += x;
        __syncthreads();
    }
    int excl = sh[t] - v;
    int sumP = sh[nbP - 1];
    if (t < nbP) blockSums[t] = excl;
    else if (t < nb) blockSums[t] = excl - sumP;
}

__global__ void k_scan3B(int* __restrict__ rowP, int* __restrict__ rowS,
                         int* __restrict__ curP, int* __restrict__ curS,
                         const int* __restrict__ blockSums, int nbP,
                         int EP, int ES,
                         float* __restrict__ dinvP, float* __restrict__ dinvS) {
    int i = blockIdx.x * blockDim.x + threadIdx.x;
    if (i < NP) {
        int r = rowP[i] + blockSums[i >> 10];
        int deg = curP[i];
        rowP[i] = r;
        curP[i] = r;
        dinvP[i] = rsqrtf((float)(deg + 1));
        if (i == 0) rowP[NP] = EP;
    } else if (i < NP + NS) {
        int l = i - NP;
        int r = rowS[l] + blockSums[(l >> 10) + nbP];
        int deg = curS[l];
        rowS[l] = r;
        curS[l] = r;
        dinvS[l] = rsqrtf((float)(deg + 1));
        if (l == 0) rowS[NS] = ES;
    }
}

__global__ void k_fillB(const int* __restrict__ eiP, int EP,
                        const int* __restrict__ eiS, int ES,
                        int* __restrict__ curP, int* __restrict__ curS,
                        int* __restrict__ srcP, int* __restrict__ srcS) {
    int e = blockIdx.x * blockDim.x + threadIdx.x;
    if (e < EP) {
        int d = eiP[EP + e];
        int p = atomicAdd(&curP[d], 1);
        srcP[p] = eiP[e];
    } else if (e < EP + ES) {
        int l = e - EP;
        int d = eiS[ES + l];
        int p = atomicAdd(&curS[d], 1);
        srcS[p] = eiS[l];
    }
}

__global__ void k_reset(int* __restrict__ curP, int* __restrict__ curS) {
    int i = blockIdx.x * blockDim.x + threadIdx.x;
    if (i < NP) curP[i] = 0;
    if (i < NS) curS[i] = 0;
}

// ======== tf32 tensor-core GEMM body (round-6 proven config) ========
#define BM 128
#define BN 64
#define BK 32
#define XPAD 40
#define WPAD 72

__device__ __forceinline__ unsigned f2tf32(float f) {
    unsigned u;
    asm("cvt.rna.tf32.f32 %0, %1;" : "=r"(u) : "f"(f));
    return u;
}

__device__ __forceinline__ void gemm_body(const float* __restrict__ X,
                                          const float* __restrict__ W,
                                          float* __restrict__ Y, int M, int K,
                                          int row0, unsigned* Xs, unsigned* Ws) {
    int tid = threadIdx.x;
    int wid = tid >> 5, lane = tid & 31;
    int lq = lane >> 2;
    int lr = lane & 3;
    int rb = (wid & 3) * 32;
    int cb = (wid >> 2) * 32;
    int nt = K / BK;

    int xr[4], xc[4];
#pragma unroll
    for (int l = 0; l < 4; l++) {
        int idx = tid + l * 256;
        xr[l] = idx >> 3;
        xc[l] = idx & 7;
    }
    int wk[2], wc[2];
#pragma unroll
    for (int l = 0; l < 2; l++) {
        int idx = tid + l * 256;
        wk[l] = idx >> 4;
        wc[l] = idx & 15;
    }

    float acc[2][4][4];
#pragma unroll
    for (int mt = 0; mt < 2; mt++)
#pragma unroll
        for (int nb = 0; nb < 4; nb++)
#pragma unroll
            for (int j = 0; j < 4; j++) acc[mt][nb][j] = 0.f;

    float4 xv[4], wv[2];
#pragma unroll
    for (int l = 0; l < 4; l++) {
        int gr = row0 + xr[l];
        xv[l] = (gr < M) ? *(const float4*)(X + (size_t)gr * K + xc[l] * 4)
                         : make_float4(0.f, 0.f, 0.f, 0.f);
    }
#pragma unroll
    for (int l = 0; l < 2; l++)
        wv[l] = *(const float4*)(W + (size_t)wk[l] * HF + wc[l] * 4);
#pragma unroll
    for (int l = 0; l < 4; l++) {
        uint4 u = make_uint4(f2tf32(xv[l].x), f2tf32(xv[l].y), f2tf32(xv[l].z), f2tf32(xv[l].w));
        *(uint4*)&Xs[xr[l] * XPAD + xc[l] * 4] = u;
    }
#pragma unroll
    for (int l = 0; l < 2; l++) {
        uint4 u = make_uint4(f2tf32(wv[l].x), f2tf32(wv[l].y), f2tf32(wv[l].z), f2tf32(wv[l].w));
        *(uint4*)&Ws[wk[l] * WPAD + wc[l] * 4] = u;
    }
    __syncthreads();

    for (int t = 0; t < nt; t++) {
        if (t + 1 < nt) {
            const float* Xn = X + (size_t)(t + 1) * BK;
            const float* Wn = W + (size_t)(t + 1) * BK * HF;
#pragma unroll
            for (int l = 0; l < 4; l++) {
                int gr = row0 + xr[l];
                xv[l] = (gr < M) ? *(const float4*)(Xn + (size_t)gr * K + xc[l] * 4)
                                 : make_float4(0.f, 0.f, 0.f, 0.f);
            }
#pragma unroll
            for (int l = 0; l < 2; l++)
                wv[l] = *(const float4*)(Wn + (size_t)wk[l] * HF + wc[l] * 4);
        }

#pragma unroll
        for (int ks = 0; ks < 4; ks++) {
            int k0 = ks * 8;
            unsigned a[2][4];
#pragma unroll
            for (int mt = 0; mt < 2; mt++) {
                int r = rb + mt * 16 + lq;
                a[mt][0] = Xs[r * XPAD + k0 + lr];
                a[mt][1] = Xs[(r + 8) * XPAD + k0 + lr];
                a[mt][2] = Xs[r * XPAD + k0 + 4 + lr];
                a[mt][3] = Xs[(r + 8) * XPAD + k0 + 4 + lr];
            }
            unsigned b[4][2];
#pragma unroll
            for (int nb = 0; nb < 4; nb++) {
                int c = cb + nb * 8 + lq;
                b[nb][0] = Ws[(k0 + lr) * WPAD + c];
                b[nb][1] = Ws[(k0 + 4 + lr) * WPAD + c];
            }
#pragma unroll
            for (int mt = 0; mt < 2; mt++)
#pragma unroll
                for (int nb = 0; nb < 4; nb++)
                    asm volatile(
                        "mma.sync.aligned.m16n8k8.row.col.f32.tf32.tf32.f32 "
                        "{%0,%1,%2,%3}, {%4,%5,%6,%7}, {%8,%9}, {%0,%1,%2,%3};"
                        : "+f"(acc[mt][nb][0]), "+f"(acc[mt][nb][1]),
                          "+f"(acc[mt][nb][2]), "+f"(acc[mt][nb][3])
                        : "r"(a[mt][0]), "r"(a[mt][1]), "r"(a[mt][2]), "r"(a[mt][3]),
                          "r"(b[nb][0]), "r"(b[nb][1]));
        }
        __syncthreads();

        if (t + 1 < nt) {
#pragma unroll
            for (int l = 0; l < 4; l++) {
                uint4 u = make_uint4(f2tf32(xv[l].x), f2tf32(xv[l].y), f2tf32(xv[l].z), f2tf32(xv[l].w));
                *(uint4*)&Xs[xr[l] * XPAD + xc[l] * 4] = u;
            }
#pragma unroll
            for (int l = 0; l < 2; l++) {
                uint4 u = make_uint4(f2tf32(wv[l].x), f2tf32(wv[l].y), f2tf32(wv[l].z), f2tf32(wv[l].w));
                *(uint4*)&Ws[wk[l] * WPAD + wc[l] * 4] = u;
            }
            __syncthreads();
        }
    }

#pragma unroll
    for (int mt = 0; mt < 2; mt++) {
#pragma unroll
        for (int nb = 0; nb < 4; nb++) {
            int r = row0 + rb + mt * 16 + lq;
            int c = cb + nb * 8 + 2 * lr;
            if (r < M)
                *(float2*)(Y + (size_t)r * HF + c) = make_float2(acc[mt][nb][0], acc[mt][nb][1]);
            if (r + 8 < M)
                *(float2*)(Y + (size_t)(r + 8) * HF + c) = make_float2(acc[mt][nb][2], acc[mt][nb][3]);
        }
    }
}

// merged GEMM: blocks [0,nb0) do segment 0, rest segment 1
__global__ __launch_bounds__(256, 2) void k_gemm2(
    const float* __restrict__ X0, const float* __restrict__ W0, float* __restrict__ Y0,
    int M0, int K0, int nb0,
    const float* __restrict__ X1, const float* __restrict__ W1, float* __restrict__ Y1,
    int M1, int K1) {
    __shared__ unsigned Xs[BM * XPAD];
    __shared__ unsigned Ws[BK * WPAD];
    int b = blockIdx.x;
    if (b < nb0) gemm_body(X0, W0, Y0, M0, K0, b * BM, Xs, Ws);
    else         gemm_body(X1, W1, Y1, M1, K1, (b - nb0) * BM, Xs, Ws);
}

// ---------------- merged GCN aggregation (P + S, 16-lane rows, 2 edges/iter) ----------------
// halfOut: 0 -> fp32 float4 rows; 1 -> fp16 rows (64 halfs = 128B, uint2/lane)
__device__ __forceinline__ void agg_node(const float* __restrict__ H, void* __restrict__ OUT,
                                         const int* __restrict__ row, const int* __restrict__ srcs,
                                         const float* __restrict__ dinv, const float* __restrict__ bias,
                                         int dst, int lane, int halfOut) {
    int half = lane >> 4;     // 0: even edges, 1: odd edges
    int hl = lane & 15;       // float4 index within 64-float row
    const float4* Hp = (const float4*)H;
    float4 a0 = make_float4(0.f, 0.f, 0.f, 0.f);
    float4 a1 = make_float4(0.f, 0.f, 0.f, 0.f);
    int s = row[dst], e = row[dst + 1];
    int i = s;
    for (; i + 4 <= e; i += 4) {
        int s0 = srcs[i + half];
        int s1 = srcs[i + 2 + half];
        float d0 = dinv[s0];
        float d1 = dinv[s1];
        float4 h0 = Hp[(size_t)s0 * 16 + hl];
        float4 h1 = Hp[(size_t)s1 * 16 + hl];
        a0.x += h0.x * d0; a0.y += h0.y * d0; a0.z += h0.z * d0; a0.w += h0.w * d0;
        a1.x += h1.x * d1; a1.y += h1.y * d1; a1.z += h1.z * d1; a1.w += h1.w * d1;
    }
    for (; i < e; i += 2) {
        int idx = i + half;
        if (idx < e) {
            int src = srcs[idx];
            float d = dinv[src];
            float4 h = Hp[(size_t)src * 16 + hl];
            a0.x += h.x * d; a0.y += h.y * d; a0.z += h.z * d; a0.w += h.w * d;
        }
    }
    float4 acc = make_float4(a0.x + a1.x, a0.y + a1.y, a0.z + a1.z, a0.w + a1.w);
    acc.x += __shfl_down_sync(0xffffffffu, acc.x, 16);
    acc.y += __shfl_down_sync(0xffffffffu, acc.y, 16);
    acc.z += __shfl_down_sync(0xffffffffu, acc.z, 16);
    acc.w += __shfl_down_sync(0xffffffffu, acc.w, 16);
    if (half == 0) {
        float di = dinv[dst];
        float4 hs = Hp[(size_t)dst * 16 + hl];   // self-loop term
        float4 b4 = ((const float4*)bias)[hl];
        float4 o;
        o.x = (acc.x + hs.x * di) * di + b4.x;
        o.y = (acc.y + hs.y * di) * di + b4.y;
        o.z = (acc.z + hs.z * di) * di + b4.z;
        o.w = (acc.w + hs.w * di) * di + b4.w;
        if (!halfOut) {
            ((float4*)OUT)[(size_t)dst * 16 + hl] = o;
        } else {
            __half2 p0 = __floats2half2_rn(o.x, o.y);
            __half2 p1 = __floats2half2_rn(o.z, o.w);
            uint2 u;
            u.x = *(unsigned*)&p0;
            u.y = *(unsigned*)&p1;
            ((uint2*)OUT)[(size_t)dst * 16 + hl] = u;
        }
    }
}

__global__ void k_aggregate2(const float* __restrict__ HP, void* __restrict__ OP,
                             const int* __restrict__ rowP, const int* __restrict__ srcP,
                             const float* __restrict__ dinvP, const float* __restrict__ biasP,
                             const float* __restrict__ HS, void* __restrict__ OS,
                             const int* __restrict__ rowS, const int* __restrict__ srcS,
                             const float* __restrict__ dinvS, const float* __restrict__ biasS,
                             int halfOut) {
    int warp = (blockIdx.x * blockDim.x + threadIdx.x) >> 5;
    int lane = threadIdx.x & 31;
    if (warp < NP) {
        agg_node(HP, OP, rowP, srcP, dinvP, biasP, warp, lane, halfOut);
    } else if (warp < NP + NS) {
        agg_node(HS, OS, rowS, srcS, dinvS, biasS, warp - NP, lane, halfOut);
    }
}

// ---- fused prep: Wc = Wproj@Wl1 (+bcomb), then W2cP/W2cS = Wp2/Ws2 @ Wc halves ----
__global__ void k_prep(const float* __restrict__ Wproj, const float* __restrict__ bproj,
                       const float* __restrict__ Wl1, const float* __restrict__ bl1,
                       const float* __restrict__ Wp2, const float* __restrict__ bp2,
                       const float* __restrict__ Ws2, const float* __restrict__ bs2,
                       float* __restrict__ Wc, float* __restrict__ W2) {
    extern __shared__ float sh[];
    float* sWl1 = sh;            // 128*64
    float* sWc  = sh + 128 * 64; // 128*64
    for (int i = threadIdx.x; i < 128 * 64; i += blockDim.x) sWl1[i] = Wl1[i];
    __syncthreads();
    for (int o = threadIdx.x; o < 128 * 64; o += blockDim.x) {
        int i = o >> 6, j = o & 63;
        float s = 0.f;
        for (int k = 0; k < 128; k++) s += Wproj[i * 128 + k] * sWl1[k * 64 + j];
        sWc[o] = s;
        Wc[o] = s;
    }
    for (int j = threadIdx.x; j < 64; j += blockDim.x) {
        float s = bl1[j];
        for (int k = 0; k < 128; k++) s += bproj[k] * sWl1[k * 64 + j];
        Wc[128 * 64 + j] = s;
    }
    __syncthreads();
    float* W2cP = W2;
    float* b2cP = W2 + 64 * 64;
    float* W2cS = W2 + 64 * 64 + 64;
    float* b2cS = W2 + 2 * 64 * 64 + 64;
    for (int o = threadIdx.x; o < 64 * 64; o += blockDim.x) {
        int i = o >> 6, j = o & 63;
        float sp = 0.f, ss = 0.f;
        for (int k = 0; k < 64; k++) {
            sp += Wp2[i * 64 + k] * sWc[k * 64 + j];
            ss += Ws2[i * 64 + k] * sWc[(64 + k) * 64 + j];
        }
        W2cP[o] = sp;
        W2cS[o] = ss;
    }
    for (int j = threadIdx.x; j < 64; j += blockDim.x) {
        float sp = 0.f, ss = 0.f;
        for (int k = 0; k < 64; k++) {
            sp += bp2[k] * sWc[k * 64 + j];
            ss += bs2[k] * sWc[(64 + k) * 64 + j];
        }
        b2cP[j] = sp;
        b2cS[j] = ss;
    }
}
#define PREP_SMEM (2 * 128 * 64 * 4)   // 64 KB

// ---------------- link predictor: fp16 features, 2 edges per warp ----------------
// out[e] = relu(Ap[ep]+As[es]+bc) . wl2 + bl2   (Ap/As are fp16 rows of 64)
__global__ void k_link(const __half* __restrict__ Ap, const __half* __restrict__ As,
                       const int* __restrict__ ep, const int* __restrict__ es,
                       const float* __restrict__ bc, const float* __restrict__ wl2,
                       const float* __restrict__ bl2, float* __restrict__ out, int EL) {
    int warp = (blockIdx.x * blockDim.x + threadIdx.x) >> 5;
    int lane = threadIdx.x & 31;
    int half = lane >> 4;
    int hl = lane & 15;
    int e = 2 * warp + half;
    if (e >= EL) return;
    int p = ep[e];
    int s = es[e];
    uint2 ua = ((const uint2*)Ap)[(size_t)p * 16 + hl];
    uint2 ub = ((const uint2*)As)[(size_t)s * 16 + hl];
    float2 a0 = __half22float2(*(__half2*)&ua.x);
    float2 a1 = __half22float2(*(__half2*)&ua.y);
    float2 b0 = __half22float2(*(__half2*)&ub.x);
    float2 b1 = __half22float2(*(__half2*)&ub.y);
    float4 c = ((const float4*)bc)[hl];
    float4 w = ((const float4*)wl2)[hl];
    float h0 = fmaxf(a0.x + b0.x + c.x, 0.f);
    float h1 = fmaxf(a0.y + b0.y + c.y, 0.f);
    float h2 = fmaxf(a1.x + b1.x + c.z, 0.f);
    float h3 = fmaxf(a1.y + b1.y + c.w, 0.f);
    float part = h0 * w.x + h1 * w.y + h2 * w.z + h3 * w.w;
#pragma unroll
    for (int off = 8; off; off >>= 1) part += __shfl_down_sync(0xffffffffu, part, off, 16);
    if (hl == 0) out[e] = part + bl2[0];
}

// ---------------- host orchestration ----------------
static inline int cdiv(int a, int b) { return (a + b - 1) / b; }

// streams/events created ONCE (pre-baseline on the correctness call) and reused.
static cudaStream_t g_s1 = nullptr, g_s2 = nullptr;
static cudaEvent_t g_evRoot, g_evCSR, g_evPrep, g_evTail;

extern "C" void kernel_launch(void* const* d_in, const int* in_sizes, int n_in,
                              void* d_out, int out_size) {
    const float* x_p  = (const float*)d_in[0];
    const float* x_s  = (const float*)d_in[1];
    const int*   ei_p = (const int*)d_in[2];
    const int*   ei_s = (const int*)d_in[3];
    const int*   ed_p = (const int*)d_in[4];
    const int*   ed_s = (const int*)d_in[5];
    const float* Wp1 = (const float*)d_in[6];
    const float* bp1 = (const float*)d_in[7];
    const float* Ws1 = (const float*)d_in[8];
    const float* bs1 = (const float*)d_in[9];
    const float* Wp2 = (const float*)d_in[10];
    const float* bp2 = (const float*)d_in[11];
    const float* Ws2 = (const float*)d_in[12];
    const float* bs2 = (const float*)d_in[13];
    const float* Wproj = (const float*)d_in[14];
    const float* bproj = (const float*)d_in[15];
    const float* Wl1 = (const float*)d_in[16];
    const float* bl1 = (const float*)d_in[17];
    const float* Wl2 = (const float*)d_in[18];
    const float* bl2 = (const float*)d_in[19];
    float* out = (float*)d_out;

    float *bufP0, *bufP1, *bufS0, *bufS1, *dinvP, *dinvS, *Wc, *W2;
    int *rowP, *rowS, *curP, *curS, *srcP, *srcS, *bsum;
    cudaGetSymbolAddress((void**)&bufP0, g_bufP0);
    cudaGetSymbolAddress((void**)&bufP1, g_bufP1);
    cudaGetSymbolAddress((void**)&bufS0, g_bufS0);
    cudaGetSymbolAddress((void**)&bufS1, g_bufS1);
    cudaGetSymbolAddress((void**)&dinvP, g_dinvP);
    cudaGetSymbolAddress((void**)&dinvS, g_dinvS);
    cudaGetSymbolAddress((void**)&rowP,  g_rowP);
    cudaGetSymbolAddress((void**)&rowS,  g_rowS);
    cudaGetSymbolAddress((void**)&curP,  g_curP);
    cudaGetSymbolAddress((void**)&curS,  g_curS);
    cudaGetSymbolAddress((void**)&srcP,  g_srcP);
    cudaGetSymbolAddress((void**)&srcS,  g_srcS);
    cudaGetSymbolAddress((void**)&Wc,    g_Wc);
    cudaGetSymbolAddress((void**)&W2,    g_W2);
    cudaGetSymbolAddress((void**)&bsum,  g_bsum);

    cudaFuncSetAttribute(k_prep, cudaFuncAttributeMaxDynamicSharedMemorySize, PREP_SMEM);

    if (g_s1 == nullptr) {
        cudaStreamCreateWithFlags(&g_s1, cudaStreamNonBlocking);
        cudaStreamCreateWithFlags(&g_s2, cudaStreamNonBlocking);
        cudaEventCreateWithFlags(&g_evRoot, cudaEventDisableTiming);
        cudaEventCreateWithFlags(&g_evCSR,  cudaEventDisableTiming);
        cudaEventCreateWithFlags(&g_evPrep, cudaEventDisableTiming);
        cudaEventCreateWithFlags(&g_evTail, cudaEventDisableTiming);
    }
    cudaStream_t s1 = g_s1, s2 = g_s2;

    const int EP = in_sizes[2] / 2;
    const int ES = in_sizes[3] / 2;
    const int EL = in_sizes[4];
    const int nbP = cdiv(NP, 1024), nbS = cdiv(NS, 1024);
    const int gP = cdiv(NP, BM), gS = cdiv(NS, BM);
    const int aggBlocks = cdiv((NP + NS) * 32, 256);

    float* W2cP = W2;
    float* b2cP = W2 + 64 * 64;
    float* W2cS = W2 + 64 * 64 + 64;
    float* b2cS = W2 + 2 * 64 * 64 + 64;

    // fork
    cudaEventRecord(g_evRoot, 0);
    cudaStreamWaitEvent(s1, g_evRoot, 0);
    cudaStreamWaitEvent(s2, g_evRoot, 0);

    // ---- s2: CSR build chain ----
    k_countB<<<cdiv(EP + ES, 256), 256, 0, s2>>>(ei_p, EP, ei_s, ES, curP, curS);
    k_scan1B<<<nbP + nbS, 1024, 0, s2>>>(curP, curS, rowP, rowS, bsum, nbP);
    k_scan2B<<<1, 1024, 0, s2>>>(bsum, nbP, nbS);
    k_scan3B<<<cdiv(NP + NS, 256), 256, 0, s2>>>(rowP, rowS, curP, curS, bsum, nbP, EP, ES, dinvP, dinvS);
    k_fillB<<<cdiv(EP + ES, 256), 256, 0, s2>>>(ei_p, EP, ei_s, ES, curP, curS, srcP, srcS);
    cudaEventRecord(g_evCSR, s2);
    k_reset<<<cdiv(NP, 256), 256, 0, s2>>>(curP, curS);
    cudaEventRecord(g_evTail, s2);

    // ---- s1: prep ----
    k_prep<<<1, 256, PREP_SMEM, s1>>>(Wproj, bproj, Wl1, bl1, Wp2, bp2, Ws2, bs2, Wc, W2);
    cudaEventRecord(g_evPrep, s1);

    // ---- s0 (main): merged P+S chain ----
    k_gemm2<<<gP + gS, 256>>>(x_p, Wp1, bufP0, NP, PD, gP,
                              x_s, Ws1, bufS0, NS, SD);
    cudaStreamWaitEvent(0, g_evCSR, 0);
    k_aggregate2<<<aggBlocks, 256>>>(bufP0, bufP1, rowP, srcP, dinvP, bp1,
                                     bufS0, bufS1, rowS, srcS, dinvS, bs1, 0);
    cudaStreamWaitEvent(0, g_evPrep, 0);
    k_gemm2<<<gP + gS, 256>>>(bufP1, W2cP, bufP0, NP, HF, gP,
                              bufS1, W2cS, bufS0, NS, HF);
    // layer-2 aggregate writes fp16 link features into bufP1/bufS1
    k_aggregate2<<<aggBlocks, 256>>>(bufP0, bufP1, rowP, srcP, dinvP, b2cP,
                                     bufS0, bufS1, rowS, srcS, dinvS, b2cS, 1);

    // ---- link prediction (fp16 features, 2 edges per warp) ----
    {
        long long threads = (long long)cdiv(EL, 2) * 32;
        int blocks = (int)((threads + 255) / 256);
        k_link<<<blocks, 256>>>((const __half*)bufP1, (const __half*)bufS1,
                                ed_p, ed_s, Wc + 128 * 64, Wl2, bl2, out, EL);
    }

    // join s2 tail (reset) back into the origin stream
    cudaStreamWaitEvent(0, g_evTail, 0);
}

// round 15
// speedup vs baseline: 1.5144x; 1.0447x over previous
#include <cuda_runtime.h>
#include <cuda_fp16.h>
#include <cstdint>
#include <cstdio>

// ---------------- problem constants ----------------
#define NP 100000
#define NS 50000
#define PD 1024
#define SD 512
#define HF 64
#define EPN 3200000
#define ESN 1600000
#define ELN 2000000

// ---------------- device scratch (static; zero-initialized at load) ----------------
// feature buffers hold fp16 rows (64 halfs = 128B); declared as float-sized for reuse
__device__ float g_bufP0[(size_t)NP * HF / 2];
__device__ float g_bufP1[(size_t)NP * HF / 2];
__device__ float g_bufS0[(size_t)NS * HF / 2];
__device__ float g_bufS1[(size_t)NS * HF / 2];
__device__ float g_dinvP[NP];
__device__ float g_dinvS[NS];
__device__ int   g_rowP[NP + 1];
__device__ int   g_rowS[NS + 1];
__device__ int   g_curP[NP];   // counts -> cursor; zero at start of each replay
__device__ int   g_curS[NS];
__device__ int   g_srcP[EPN];
__device__ int   g_srcS[ESN];
__device__ float g_Wc[128 * 64 + 64];      // Wcomb [128,64] row-major, then bcomb[64]
__device__ float g_W2[2 * (64 * 64 + 64)]; // W2cP[64x64], b2cP[64], W2cS[64x64], b2cS[64]
__device__ int   g_bsum[256];

// ================= CSR build (both graphs in shared kernels) =================
__global__ void k_countB(const int* __restrict__ eiP, int EP,
                         const int* __restrict__ eiS, int ES,
                         int* __restrict__ cntP, int* __restrict__ cntS) {
    int e = blockIdx.x * blockDim.x + threadIdx.x;
    if (e < EP) {
        atomicAdd(&cntP[eiP[EP + e]], 1);
    } else if (e < EP + ES) {
        int l = e - EP;
        atomicAdd(&cntS[eiS[ES + l]], 1);
    }
}

__global__ void k_scan1B(const int* __restrict__ cntP, const int* __restrict__ cntS,
                         int* __restrict__ rowP, int* __restrict__ rowS,
                         int* __restrict__ blockSums, int nbP) {
    __shared__ int sh[1024];
    int b = blockIdx.x;
    const int* cnt;
    int* rowOut;
    int N, local0;
    if (b < nbP) { cnt = cntP; rowOut = rowP; N = NP; local0 = b * 1024; }
    else         { cnt = cntS; rowOut = rowS; N = NS; local0 = (b - nbP) * 1024; }
    int i = local0 + threadIdx.x;
    int v = (i < N) ? cnt[i] : 0;
    sh[threadIdx.x] = v;
    __syncthreads();
    for (int off = 1; off < 1024; off <<= 1) {
        int t = 0;
        if ((int)threadIdx.x >= off) t = sh[threadIdx.x - off];
        __syncthreads();
        sh[threadIdx.x] += t;
        __syncthreads();
    }
    int incl = sh[threadIdx.x];
    if (i < N) rowOut[i] = incl - v;
    if (threadIdx.x == 1023) blockSums[b] = incl;
}

__global__ void k_scan2B(int* __restrict__ blockSums, int nbP, int nbS) {
    __shared__ int sh[1024];
    int nb = nbP + nbS;
    int t = threadIdx.x;
    int v = (t < nb) ? blockSums[t] : 0;
    sh[t] = v;
    __syncthreads();
    for (int off = 1; off < 1024; off <<= 1) {
        int x = 0;
        if (t >= off) x = sh[t - off];
        __syncthreads();
        sh[t] += x;
        __syncthreads();
    }
    int excl = sh[t] - v;
    int sumP = sh[nbP - 1];
    if (t < nbP) blockSums[t] = excl;
    else if (t < nb) blockSums[t] = excl - sumP;
}

__global__ void k_scan3B(int* __restrict__ rowP, int* __restrict__ rowS,
                         int* __restrict__ curP, int* __restrict__ curS,
                         const int* __restrict__ blockSums, int nbP,
                         int EP, int ES,
                         float* __restrict__ dinvP, float* __restrict__ dinvS) {
    int i = blockIdx.x * blockDim.x + threadIdx.x;
    if (i < NP) {
        int r = rowP[i] + blockSums[i >> 10];
        int deg = curP[i];
        rowP[i] = r;
        curP[i] = r;
        dinvP[i] = rsqrtf((float)(deg + 1));
        if (i == 0) rowP[NP] = EP;
    } else if (i < NP + NS) {
        int l = i - NP;
        int r = rowS[l] + blockSums[(l >> 10) + nbP];
        int deg = curS[l];
        rowS[l] = r;
        curS[l] = r;
        dinvS[l] = rsqrtf((float)(deg + 1));
        if (l == 0) rowS[NS] = ES;
    }
}

__global__ void k_fillB(const int* __restrict__ eiP, int EP,
                        const int* __restrict__ eiS, int ES,
                        int* __restrict__ curP, int* __restrict__ curS,
                        int* __restrict__ srcP, int* __restrict__ srcS) {
    int e = blockIdx.x * blockDim.x + threadIdx.x;
    if (e < EP) {
        int d = eiP[EP + e];
        int p = atomicAdd(&curP[d], 1);
        srcP[p] = eiP[e];
    } else if (e < EP + ES) {
        int l = e - EP;
        int d = eiS[ES + l];
        int p = atomicAdd(&curS[d], 1);
        srcS[p] = eiS[l];
    }
}

__global__ void k_reset(int* __restrict__ curP, int* __restrict__ curS) {
    int i = blockIdx.x * blockDim.x + threadIdx.x;
    if (i < NP) curP[i] = 0;
    if (i < NS) curS[i] = 0;
}

// ======== tf32 tensor-core GEMM bodies (round-6 proven tiling) ========
#define BM 128
#define BN 64
#define BK 32
#define XPAD 40
#define WPAD 72

__device__ __forceinline__ unsigned f2tf32(float f) {
    unsigned u;
    asm("cvt.rna.tf32.f32 %0, %1;" : "=r"(u) : "f"(f));
    return u;
}

// shared compute core: Xs/Ws tiles -> acc; then fp16 epilogue
__device__ __forceinline__ void mma_tile(const unsigned* Xs, const unsigned* Ws,
                                         int rb, int cb, int lq, int lr,
                                         float acc[2][4][4]) {
#pragma unroll
    for (int ks = 0; ks < 4; ks++) {
        int k0 = ks * 8;
        unsigned a[2][4];
#pragma unroll
        for (int mt = 0; mt < 2; mt++) {
            int r = rb + mt * 16 + lq;
            a[mt][0] = Xs[r * XPAD + k0 + lr];
            a[mt][1] = Xs[(r + 8) * XPAD + k0 + lr];
            a[mt][2] = Xs[r * XPAD + k0 + 4 + lr];
            a[mt][3] = Xs[(r + 8) * XPAD + k0 + 4 + lr];
        }
        unsigned b[4][2];
#pragma unroll
        for (int nb = 0; nb < 4; nb++) {
            int c = cb + nb * 8 + lq;
            b[nb][0] = Ws[(k0 + lr) * WPAD + c];
            b[nb][1] = Ws[(k0 + 4 + lr) * WPAD + c];
        }
#pragma unroll
        for (int mt = 0; mt < 2; mt++)
#pragma unroll
            for (int nb = 0; nb < 4; nb++)
                asm volatile(
                    "mma.sync.aligned.m16n8k8.row.col.f32.tf32.tf32.f32 "
                    "{%0,%1,%2,%3}, {%4,%5,%6,%7}, {%8,%9}, {%0,%1,%2,%3};"
                    : "+f"(acc[mt][nb][0]), "+f"(acc[mt][nb][1]),
                      "+f"(acc[mt][nb][2]), "+f"(acc[mt][nb][3])
                    : "r"(a[mt][0]), "r"(a[mt][1]), "r"(a[mt][2]), "r"(a[mt][3]),
                      "r"(b[nb][0]), "r"(b[nb][1]));
    }
}

__device__ __forceinline__ void epilogue_h(__half* Y, int M, int row0, int rb, int cb,
                                           int lq, int lr, float acc[2][4][4]) {
#pragma unroll
    for (int mt = 0; mt < 2; mt++) {
#pragma unroll
        for (int nb = 0; nb < 4; nb++) {
            int r = row0 + rb + mt * 16 + lq;
            int c = cb + nb * 8 + 2 * lr;   // even
            if (r < M)
                ((__half2*)Y)[(size_t)r * 32 + (c >> 1)] =
                    __floats2half2_rn(acc[mt][nb][0], acc[mt][nb][1]);
            if (r + 8 < M)
                ((__half2*)Y)[(size_t)(r + 8) * 32 + (c >> 1)] =
                    __floats2half2_rn(acc[mt][nb][2], acc[mt][nb][3]);
        }
    }
}

// fp32 X -> fp16 Y (layer 1)
__device__ __forceinline__ void gemm_body(const float* __restrict__ X,
                                          const float* __restrict__ W,
                                          __half* __restrict__ Y, int M, int K,
                                          int row0, unsigned* Xs, unsigned* Ws) {
    int tid = threadIdx.x;
    int wid = tid >> 5, lane = tid & 31;
    int lq = lane >> 2, lr = lane & 3;
    int rb = (wid & 3) * 32, cb = (wid >> 2) * 32;
    int nt = K / BK;

    int xr[4], xc[4];
#pragma unroll
    for (int l = 0; l < 4; l++) {
        int idx = tid + l * 256;
        xr[l] = idx >> 3;
        xc[l] = idx & 7;
    }
    int wk[2], wc[2];
#pragma unroll
    for (int l = 0; l < 2; l++) {
        int idx = tid + l * 256;
        wk[l] = idx >> 4;
        wc[l] = idx & 15;
    }

    float acc[2][4][4];
#pragma unroll
    for (int mt = 0; mt < 2; mt++)
#pragma unroll
        for (int nb = 0; nb < 4; nb++)
#pragma unroll
            for (int j = 0; j < 4; j++) acc[mt][nb][j] = 0.f;

    float4 xv[4], wv[2];
#pragma unroll
    for (int l = 0; l < 4; l++) {
        int gr = row0 + xr[l];
        xv[l] = (gr < M) ? *(const float4*)(X + (size_t)gr * K + xc[l] * 4)
                         : make_float4(0.f, 0.f, 0.f, 0.f);
    }
#pragma unroll
    for (int l = 0; l < 2; l++)
        wv[l] = *(const float4*)(W + (size_t)wk[l] * HF + wc[l] * 4);
#pragma unroll
    for (int l = 0; l < 4; l++) {
        uint4 u = make_uint4(f2tf32(xv[l].x), f2tf32(xv[l].y), f2tf32(xv[l].z), f2tf32(xv[l].w));
        *(uint4*)&Xs[xr[l] * XPAD + xc[l] * 4] = u;
    }
#pragma unroll
    for (int l = 0; l < 2; l++) {
        uint4 u = make_uint4(f2tf32(wv[l].x), f2tf32(wv[l].y), f2tf32(wv[l].z), f2tf32(wv[l].w));
        *(uint4*)&Ws[wk[l] * WPAD + wc[l] * 4] = u;
    }
    __syncthreads();

    for (int t = 0; t < nt; t++) {
        if (t + 1 < nt) {
            const float* Xn = X + (size_t)(t + 1) * BK;
            const float* Wn = W + (size_t)(t + 1) * BK * HF;
#pragma unroll
            for (int l = 0; l < 4; l++) {
                int gr = row0 + xr[l];
                xv[l] = (gr < M) ? *(const float4*)(Xn + (size_t)gr * K + xc[l] * 4)
                                 : make_float4(0.f, 0.f, 0.f, 0.f);
            }
#pragma unroll
            for (int l = 0; l < 2; l++)
                wv[l] = *(const float4*)(Wn + (size_t)wk[l] * HF + wc[l] * 4);
        }
        mma_tile(Xs, Ws, rb, cb, lq, lr, acc);
        __syncthreads();
        if (t + 1 < nt) {
#pragma unroll
            for (int l = 0; l < 4; l++) {
                uint4 u = make_uint4(f2tf32(xv[l].x), f2tf32(xv[l].y), f2tf32(xv[l].z), f2tf32(xv[l].w));
                *(uint4*)&Xs[xr[l] * XPAD + xc[l] * 4] = u;
            }
#pragma unroll
            for (int l = 0; l < 2; l++) {
                uint4 u = make_uint4(f2tf32(wv[l].x), f2tf32(wv[l].y), f2tf32(wv[l].z), f2tf32(wv[l].w));
                *(uint4*)&Ws[wk[l] * WPAD + wc[l] * 4] = u;
            }
            __syncthreads();
        }
    }
    epilogue_h(Y, M, row0, rb, cb, lq, lr, acc);
}

// fp16 X -> fp16 Y (layer 2, K=64: 2 tiles, no pipelining needed)
__device__ __forceinline__ void gemm_body_h(const __half* __restrict__ X,
                                            const float* __restrict__ W,
                                            __half* __restrict__ Y, int M, int K,
                                            int row0, unsigned* Xs, unsigned* Ws) {
    int tid = threadIdx.x;
    int wid = tid >> 5, lane = tid & 31;
    int lq = lane >> 2, lr = lane & 3;
    int rb = (wid & 3) * 32, cb = (wid >> 2) * 32;
    int nt = K / BK;

    // X: 128 rows x 4 chunks(16B = 8 halfs) = 512, 2/thread
    int xr[2], xc[2];
#pragma unroll
    for (int l = 0; l < 2; l++) {
        int idx = tid + l * 256;
        xr[l] = idx >> 2;
        xc[l] = idx & 3;
    }
    int wk[2], wc[2];
#pragma unroll
    for (int l = 0; l < 2; l++) {
        int idx = tid + l * 256;
        wk[l] = idx >> 4;
        wc[l] = idx & 15;
    }

    float acc[2][4][4];
#pragma unroll
    for (int mt = 0; mt < 2; mt++)
#pragma unroll
        for (int nb = 0; nb < 4; nb++)
#pragma unroll
            for (int j = 0; j < 4; j++) acc[mt][nb][j] = 0.f;

    for (int t = 0; t < nt; t++) {
        // load + convert X tile
#pragma unroll
        for (int l = 0; l < 2; l++) {
            int gr = row0 + xr[l];
            uint4 v = make_uint4(0u, 0u, 0u, 0u);
            if (gr < M)
                v = *(const uint4*)(X + (size_t)gr * K + t * BK + xc[l] * 8);
            const __half2* hp = (const __half2*)&v;
            unsigned o[8];
#pragma unroll
            for (int j = 0; j < 4; j++) {
                float2 f = __half22float2(hp[j]);
                o[2 * j] = f2tf32(f.x);
                o[2 * j + 1] = f2tf32(f.y);
            }
            *(uint4*)&Xs[xr[l] * XPAD + xc[l] * 8]     = make_uint4(o[0], o[1], o[2], o[3]);
            *(uint4*)&Xs[xr[l] * XPAD + xc[l] * 8 + 4] = make_uint4(o[4], o[5], o[6], o[7]);
        }
        // load + convert W tile
#pragma unroll
        for (int l = 0; l < 2; l++) {
            float4 w = *(const float4*)(W + (size_t)(t * BK + wk[l]) * HF + wc[l] * 4);
            uint4 u = make_uint4(f2tf32(w.x), f2tf32(w.y), f2tf32(w.z), f2tf32(w.w));
            *(uint4*)&Ws[wk[l] * WPAD + wc[l] * 4] = u;
        }
        __syncthreads();
        mma_tile(Xs, Ws, rb, cb, lq, lr, acc);
        __syncthreads();
    }
    epilogue_h(Y, M, row0, rb, cb, lq, lr, acc);
}

// merged layer-1 GEMM: blocks [0,nb0) segment 0, rest segment 1
__global__ __launch_bounds__(256, 2) void k_gemm2(
    const float* __restrict__ X0, const float* __restrict__ W0, __half* __restrict__ Y0,
    int M0, int K0, int nb0,
    const float* __restrict__ X1, const float* __restrict__ W1, __half* __restrict__ Y1,
    int M1, int K1) {
    __shared__ unsigned Xs[BM * XPAD];
    __shared__ unsigned Ws[BK * WPAD];
    int b = blockIdx.x;
    if (b < nb0) gemm_body(X0, W0, Y0, M0, K0, b * BM, Xs, Ws);
    else         gemm_body(X1, W1, Y1, M1, K1, (b - nb0) * BM, Xs, Ws);
}

// merged layer-2 GEMM (fp16 in/out)
__global__ __launch_bounds__(256, 2) void k_gemm2h(
    const __half* __restrict__ X0, const float* __restrict__ W0, __half* __restrict__ Y0,
    int M0, int nb0,
    const __half* __restrict__ X1, const float* __restrict__ W1, __half* __restrict__ Y1,
    int M1) {
    __shared__ unsigned Xs[BM * XPAD];
    __shared__ unsigned Ws[BK * WPAD];
    int b = blockIdx.x;
    if (b < nb0) gemm_body_h(X0, W0, Y0, M0, HF, b * BM, Xs, Ws);
    else         gemm_body_h(X1, W1, Y1, M1, HF, (b - nb0) * BM, Xs, Ws);
}

// ---------------- merged GCN aggregation (fp16 in, fp16 out) ----------------
__device__ __forceinline__ void agg_node(const __half* __restrict__ H, __half* __restrict__ OUT,
                                         const int* __restrict__ row, const int* __restrict__ srcs,
                                         const float* __restrict__ dinv, const float* __restrict__ bias,
                                         int dst, int lane) {
    int half = lane >> 4;     // 0: even edges, 1: odd edges
    int hl = lane & 15;       // uint2 index within 128B row
    const uint2* Hp = (const uint2*)H;
    float4 a0 = make_float4(0.f, 0.f, 0.f, 0.f);
    float4 a1 = make_float4(0.f, 0.f, 0.f, 0.f);
    int s = row[dst], e = row[dst + 1];
    int i = s;
    for (; i + 4 <= e; i += 4) {
        int s0 = srcs[i + half];
        int s1 = srcs[i + 2 + half];
        float d0 = dinv[s0];
        float d1 = dinv[s1];
        uint2 u0 = Hp[(size_t)s0 * 16 + hl];
        uint2 u1 = Hp[(size_t)s1 * 16 + hl];
        float2 f00 = __half22float2(*(__half2*)&u0.x);
        float2 f01 = __half22float2(*(__half2*)&u0.y);
        float2 f10 = __half22float2(*(__half2*)&u1.x);
        float2 f11 = __half22float2(*(__half2*)&u1.y);
        a0.x += f00.x * d0; a0.y += f00.y * d0; a0.z += f01.x * d0; a0.w += f01.y * d0;
        a1.x += f10.x * d1; a1.y += f10.y * d1; a1.z += f11.x * d1; a1.w += f11.y * d1;
    }
    for (; i < e; i += 2) {
        int idx = i + half;
        if (idx < e) {
            int src = srcs[idx];
            float d = dinv[src];
            uint2 u = Hp[(size_t)src * 16 + hl];
            float2 f0 = __half22float2(*(__half2*)&u.x);
            float2 f1 = __half22float2(*(__half2*)&u.y);
            a0.x += f0.x * d; a0.y += f0.y * d; a0.z += f1.x * d; a0.w += f1.y * d;
        }
    }
    float4 acc = make_float4(a0.x + a1.x, a0.y + a1.y, a0.z + a1.z, a0.w + a1.w);
    acc.x += __shfl_down_sync(0xffffffffu, acc.x, 16);
    acc.y += __shfl_down_sync(0xffffffffu, acc.y, 16);
    acc.z += __shfl_down_sync(0xffffffffu, acc.z, 16);
    acc.w += __shfl_down_sync(0xffffffffu, acc.w, 16);
    if (half == 0) {
        float di = dinv[dst];
        uint2 us = Hp[(size_t)dst * 16 + hl];   // self-loop term
        float2 s0 = __half22float2(*(__half2*)&us.x);
        float2 s1 = __half22float2(*(__half2*)&us.y);
        float4 b4 = ((const float4*)bias)[hl];
        float4 o;
        o.x = (acc.x + s0.x * di) * di + b4.x;
        o.y = (acc.y + s0.y * di) * di + b4.y;
        o.z = (acc.z + s1.x * di) * di + b4.z;
        o.w = (acc.w + s1.y * di) * di + b4.w;
        __half2 p0 = __floats2half2_rn(o.x, o.y);
        __half2 p1 = __floats2half2_rn(o.z, o.w);
        uint2 u;
        u.x = *(unsigned*)&p0;
        u.y = *(unsigned*)&p1;
        ((uint2*)OUT)[(size_t)dst * 16 + hl] = u;
    }
}

__global__ void k_aggregate2(const __half* __restrict__ HP, __half* __restrict__ OP,
                             const int* __restrict__ rowP, const int* __restrict__ srcP,
                             const float* __restrict__ dinvP, const float* __restrict__ biasP,
                             const __half* __restrict__ HS, __half* __restrict__ OS,
                             const int* __restrict__ rowS, const int* __restrict__ srcS,
                             const float* __restrict__ dinvS, const float* __restrict__ biasS) {
    int warp = (blockIdx.x * blockDim.x + threadIdx.x) >> 5;
    int lane = threadIdx.x & 31;
    if (warp < NP) {
        agg_node(HP, OP, rowP, srcP, dinvP, biasP, warp, lane);
    } else if (warp < NP + NS) {
        agg_node(HS, OS, rowS, srcS, dinvS, biasS, warp - NP, lane);
    }
}

// ---- fused prep: Wc = Wproj@Wl1 (+bcomb), then W2cP/W2cS = Wp2/Ws2 @ Wc halves ----
__global__ void k_prep(const float* __restrict__ Wproj, const float* __restrict__ bproj,
                       const float* __restrict__ Wl1, const float* __restrict__ bl1,
                       const float* __restrict__ Wp2, const float* __restrict__ bp2,
                       const float* __restrict__ Ws2, const float* __restrict__ bs2,
                       float* __restrict__ Wc, float* __restrict__ W2) {
    extern __shared__ float sh[];
    float* sWl1 = sh;            // 128*64
    float* sWc  = sh + 128 * 64; // 128*64
    for (int i = threadIdx.x; i < 128 * 64; i += blockDim.x) sWl1[i] = Wl1[i];
    __syncthreads();
    for (int o = threadIdx.x; o < 128 * 64; o += blockDim.x) {
        int i = o >> 6, j = o & 63;
        float s = 0.f;
        for (int k = 0; k < 128; k++) s += Wproj[i * 128 + k] * sWl1[k * 64 + j];
        sWc[o] = s;
        Wc[o] = s;
    }
    for (int j = threadIdx.x; j < 64; j += blockDim.x) {
        float s = bl1[j];
        for (int k = 0; k < 128; k++) s += bproj[k] * sWl1[k * 64 + j];
        Wc[128 * 64 + j] = s;
    }
    __syncthreads();
    float* W2cP = W2;
    float* b2cP = W2 + 64 * 64;
    float* W2cS = W2 + 64 * 64 + 64;
    float* b2cS = W2 + 2 * 64 * 64 + 64;
    for (int o = threadIdx.x; o < 64 * 64; o += blockDim.x) {
        int i = o >> 6, j = o & 63;
        float sp = 0.f, ss = 0.f;
        for (int k = 0; k < 64; k++) {
            sp += Wp2[i * 64 + k] * sWc[k * 64 + j];
            ss += Ws2[i * 64 + k] * sWc[(64 + k) * 64 + j];
        }
        W2cP[o] = sp;
        W2cS[o] = ss;
    }
    for (int j = threadIdx.x; j < 64; j += blockDim.x) {
        float sp = 0.f, ss = 0.f;
        for (int k = 0; k < 64; k++) {
            sp += bp2[k] * sWc[k * 64 + j];
            ss += bs2[k] * sWc[(64 + k) * 64 + j];
        }
        b2cP[j] = sp;
        b2cS[j] = ss;
    }
}
#define PREP_SMEM (2 * 128 * 64 * 4)   // 64 KB

// ---------------- link predictor: fp16 features, 2 edges per warp ----------------
__global__ void k_link(const __half* __restrict__ Ap, const __half* __restrict__ As,
                       const int* __restrict__ ep, const int* __restrict__ es,
                       const float* __restrict__ bc, const float* __restrict__ wl2,
                       const float* __restrict__ bl2, float* __restrict__ out, int EL) {
    int warp = (blockIdx.x * blockDim.x + threadIdx.x) >> 5;
    int lane = threadIdx.x & 31;
    int half = lane >> 4;
    int hl = lane & 15;
    int e = 2 * warp + half;
    if (e >= EL) return;
    int p = ep[e];
    int s = es[e];
    uint2 ua = ((const uint2*)Ap)[(size_t)p * 16 + hl];
    uint2 ub = ((const uint2*)As)[(size_t)s * 16 + hl];
    float2 a0 = __half22float2(*(__half2*)&ua.x);
    float2 a1 = __half22float2(*(__half2*)&ua.y);
    float2 b0 = __half22float2(*(__half2*)&ub.x);
    float2 b1 = __half22float2(*(__half2*)&ub.y);
    float4 c = ((const float4*)bc)[hl];
    float4 w = ((const float4*)wl2)[hl];
    float h0 = fmaxf(a0.x + b0.x + c.x, 0.f);
    float h1 = fmaxf(a0.y + b0.y + c.y, 0.f);
    float h2 = fmaxf(a1.x + b1.x + c.z, 0.f);
    float h3 = fmaxf(a1.y + b1.y + c.w, 0.f);
    float part = h0 * w.x + h1 * w.y + h2 * w.z + h3 * w.w;
#pragma unroll
    for (int off = 8; off; off >>= 1) part += __shfl_down_sync(0xffffffffu, part, off, 16);
    if (hl == 0) out[e] = part + bl2[0];
}

// ---------------- host orchestration ----------------
static inline int cdiv(int a, int b) { return (a + b - 1) / b; }

// streams/events created ONCE (pre-baseline on the correctness call) and reused.
static cudaStream_t g_s1 = nullptr, g_s2 = nullptr;
static cudaEvent_t g_evRoot, g_evCSR, g_evPrep, g_evTail;

extern "C" void kernel_launch(void* const* d_in, const int* in_sizes, int n_in,
                              void* d_out, int out_size) {
    const float* x_p  = (const float*)d_in[0];
    const float* x_s  = (const float*)d_in[1];
    const int*   ei_p = (const int*)d_in[2];
    const int*   ei_s = (const int*)d_in[3];
    const int*   ed_p = (const int*)d_in[4];
    const int*   ed_s = (const int*)d_in[5];
    const float* Wp1 = (const float*)d_in[6];
    const float* bp1 = (const float*)d_in[7];
    const float* Ws1 = (const float*)d_in[8];
    const float* bs1 = (const float*)d_in[9];
    const float* Wp2 = (const float*)d_in[10];
    const float* bp2 = (const float*)d_in[11];
    const float* Ws2 = (const float*)d_in[12];
    const float* bs2 = (const float*)d_in[13];
    const float* Wproj = (const float*)d_in[14];
    const float* bproj = (const float*)d_in[15];
    const float* Wl1 = (const float*)d_in[16];
    const float* bl1 = (const float*)d_in[17];
    const float* Wl2 = (const float*)d_in[18];
    const float* bl2 = (const float*)d_in[19];
    float* out = (float*)d_out;

    float *dinvP, *dinvS, *Wc, *W2;
    __half *bufP0, *bufP1, *bufS0, *bufS1;
    int *rowP, *rowS, *curP, *curS, *srcP, *srcS, *bsum;
    cudaGetSymbolAddress((void**)&bufP0, g_bufP0);
    cudaGetSymbolAddress((void**)&bufP1, g_bufP1);
    cudaGetSymbolAddress((void**)&bufS0, g_bufS0);
    cudaGetSymbolAddress((void**)&bufS1, g_bufS1);
    cudaGetSymbolAddress((void**)&dinvP, g_dinvP);
    cudaGetSymbolAddress((void**)&dinvS, g_dinvS);
    cudaGetSymbolAddress((void**)&rowP,  g_rowP);
    cudaGetSymbolAddress((void**)&rowS,  g_rowS);
    cudaGetSymbolAddress((void**)&curP,  g_curP);
    cudaGetSymbolAddress((void**)&curS,  g_curS);
    cudaGetSymbolAddress((void**)&srcP,  g_srcP);
    cudaGetSymbolAddress((void**)&srcS,  g_srcS);
    cudaGetSymbolAddress((void**)&Wc,    g_Wc);
    cudaGetSymbolAddress((void**)&W2,    g_W2);
    cudaGetSymbolAddress((void**)&bsum,  g_bsum);

    cudaFuncSetAttribute(k_prep, cudaFuncAttributeMaxDynamicSharedMemorySize, PREP_SMEM);

    if (g_s1 == nullptr) {
        cudaStreamCreateWithFlags(&g_s1, cudaStreamNonBlocking);
        cudaStreamCreateWithFlags(&g_s2, cudaStreamNonBlocking);
        cudaEventCreateWithFlags(&g_evRoot, cudaEventDisableTiming);
        cudaEventCreateWithFlags(&g_evCSR,  cudaEventDisableTiming);
        cudaEventCreateWithFlags(&g_evPrep, cudaEventDisableTiming);
        cudaEventCreateWithFlags(&g_evTail, cudaEventDisableTiming);
    }
    cudaStream_t s1 = g_s1, s2 = g_s2;

    const int EP = in_sizes[2] / 2;
    const int ES = in_sizes[3] / 2;
    const int EL = in_sizes[4];
    const int nbP = cdiv(NP, 1024), nbS = cdiv(NS, 1024);
    const int gP = cdiv(NP, BM), gS = cdiv(NS, BM);
    const int aggBlocks = cdiv((NP + NS) * 32, 256);

    float* W2cP = W2;
    float* b2cP = W2 + 64 * 64;
    float* W2cS = W2 + 64 * 64 + 64;
    float* b2cS = W2 + 2 * 64 * 64 + 64;

    // fork
    cudaEventRecord(g_evRoot, 0);
    cudaStreamWaitEvent(s1, g_evRoot, 0);
    cudaStreamWaitEvent(s2, g_evRoot, 0);

    // ---- s2: CSR build chain ----
    k_countB<<<cdiv(EP + ES, 256), 256, 0, s2>>>(ei_p, EP, ei_s, ES, curP, curS);
    k_scan1B<<<nbP + nbS, 1024, 0, s2>>>(curP, curS, rowP, rowS, bsum, nbP);
    k_scan2B<<<1, 1024, 0, s2>>>(bsum, nbP, nbS);
    k_scan3B<<<cdiv(NP + NS, 256), 256, 0, s2>>>(rowP, rowS, curP, curS, bsum, nbP, EP, ES, dinvP, dinvS);
    k_fillB<<<cdiv(EP + ES, 256), 256, 0, s2>>>(ei_p, EP, ei_s, ES, curP, curS, srcP, srcS);
    cudaEventRecord(g_evCSR, s2);
    k_reset<<<cdiv(NP, 256), 256, 0, s2>>>(curP, curS);
    cudaEventRecord(g_evTail, s2);

    // ---- s1: prep ----
    k_prep<<<1, 256, PREP_SMEM, s1>>>(Wproj, bproj, Wl1, bl1, Wp2, bp2, Ws2, bs2, Wc, W2);
    cudaEventRecord(g_evPrep, s1);

    // ---- s0 (main): merged P+S chain (all internal features fp16) ----
    k_gemm2<<<gP + gS, 256>>>(x_p, Wp1, bufP0, NP, PD, gP,
                              x_s, Ws1, bufS0, NS, SD);
    cudaStreamWaitEvent(0, g_evCSR, 0);
    k_aggregate2<<<aggBlocks, 256>>>(bufP0, bufP1, rowP, srcP, dinvP, bp1,
                                     bufS0, bufS1, rowS, srcS, dinvS, bs1);
    cudaStreamWaitEvent(0, g_evPrep, 0);
    k_gemm2h<<<gP + gS, 256>>>(bufP1, W2cP, bufP0, NP, gP,
                               bufS1, W2cS, bufS0, NS);
    k_aggregate2<<<aggBlocks, 256>>>(bufP0, bufP1, rowP, srcP, dinvP, b2cP,
                                     bufS0, bufS1, rowS, srcS, dinvS, b2cS);

    // ---- link prediction (fp16 features, 2 edges per warp) ----
    {
        long long threads = (long long)cdiv(EL, 2) * 32;
        int blocks = (int)((threads + 255) / 256);
        k_link<<<blocks, 256>>>(bufP1, bufS1, ed_p, ed_s, Wc + 128 * 64, Wl2, bl2, out, EL);
    }

    // join s2 tail (reset) back into the origin stream
    cudaStreamWaitEvent(0, g_evTail, 0);
}